// round 1
// baseline (speedup 1.0000x reference)
#include <cuda_runtime.h>
#include <cuda_bf16.h>
#include <math.h>

// ---------------- problem constants ----------------
#define BATCH   64
#define CDIM    384
#define HEADS   6
#define HD      64
#define MLPD    1536
#define LAYERS  12
#define NPATCH  196
#define MAXN    197
#define NCLS    100
#define EPSLN   1e-6f
#define SCALE   0.125f   // 64^-0.5

// ---------------- device scratch (no cudaMalloc allowed) ----------------
__device__ float g_h0[(size_t)BATCH * MAXN * CDIM];
__device__ float g_h1[(size_t)BATCH * MAXN * CDIM];
__device__ float g_ln[(size_t)BATCH * MAXN * CDIM];
__device__ float g_qkv[(size_t)BATCH * MAXN * 3 * CDIM];
__device__ float g_attn[(size_t)BATCH * HEADS * MAXN * MAXN];
__device__ float g_ao[(size_t)BATCH * MAXN * CDIM];
__device__ float g_mlp[(size_t)BATCH * MAXN * MLPD];
__device__ float g_patch[(size_t)BATCH * NPATCH * 768];
__device__ float g_scores[BATCH * NPATCH];
__device__ int   g_idx[BATCH * NPATCH];

// ---------------- patchify: x[B,3,224,224] -> p[B,196,768] ----------------
__global__ void patchify_kernel(const float* __restrict__ x, float* __restrict__ p) {
    int i = blockIdx.x * 256 + threadIdx.x;
    const int TOT = BATCH * NPATCH * 768;
    if (i >= TOT) return;
    int k  = i % 768;
    int tt = (i / 768) % NPATCH;
    int b  = i / (768 * NPATCH);
    int ch = k >> 8;
    int py = (k >> 4) & 15;
    int px = k & 15;
    int gy = tt / 14, gx = tt % 14;
    p[i] = x[(((size_t)b * 3 + ch) * 224 + gy * 16 + py) * 224 + gx * 16 + px];
}

// ---------------- assemble: cls + patch-embed + pos ----------------
__global__ void assemble_kernel(const float* __restrict__ pe, const float* __restrict__ cls,
                                const float* __restrict__ pos, float* __restrict__ h) {
    int i = blockIdx.x * 256 + threadIdx.x;
    const int TOT = BATCH * MAXN * CDIM;
    if (i >= TOT) return;
    int c = i % CDIM;
    int r = (i / CDIM) % MAXN;
    int b = i / (CDIM * MAXN);
    float v = (r == 0) ? cls[c] : pe[((size_t)b * NPATCH + (r - 1)) * CDIM + c];
    h[i] = v + pos[r * CDIM + c];
}

// ---------------- generic fp32 GEMM: C = A[M,K] @ W[K,N] + bias (+res | gelu) ----
// EPI: 0 = bias, 1 = bias + residual, 2 = bias + exact GELU
template<int EPI>
__global__ __launch_bounds__(256)
void gemm_kernel(const float* __restrict__ A, const float* __restrict__ W,
                 const float* __restrict__ bias, const float* __restrict__ res,
                 float* __restrict__ Cout, int M, int K, int Nout) {
    __shared__ float As[16][65];
    __shared__ float Bs[16][64];
    int m0 = blockIdx.y * 64;
    int n0 = blockIdx.x * 64;
    int t  = threadIdx.x;
    int tx = t & 15, ty = t >> 4;
    float acc[4][4] = {};
    for (int k0 = 0; k0 < K; k0 += 16) {
#pragma unroll
        for (int l = 0; l < 4; l++) {
            int idx = t + l * 256;
            int m = idx >> 4, kk = idx & 15;
            int gm = m0 + m;
            As[kk][m] = (gm < M) ? A[(size_t)gm * K + k0 + kk] : 0.f;
        }
#pragma unroll
        for (int l = 0; l < 4; l++) {
            int idx = t + l * 256;
            int kk = idx >> 6, n = idx & 63;
            int gn = n0 + n;
            Bs[kk][n] = (gn < Nout) ? W[(size_t)(k0 + kk) * Nout + gn] : 0.f;
        }
        __syncthreads();
#pragma unroll
        for (int kk = 0; kk < 16; kk++) {
            float a[4], bv[4];
#pragma unroll
            for (int i = 0; i < 4; i++) a[i] = As[kk][ty + 16 * i];
#pragma unroll
            for (int j = 0; j < 4; j++) bv[j] = Bs[kk][tx + 16 * j];
#pragma unroll
            for (int i = 0; i < 4; i++)
#pragma unroll
                for (int j = 0; j < 4; j++)
                    acc[i][j] += a[i] * bv[j];
        }
        __syncthreads();
    }
#pragma unroll
    for (int i = 0; i < 4; i++) {
        int gm = m0 + ty + 16 * i;
        if (gm >= M) continue;
#pragma unroll
        for (int j = 0; j < 4; j++) {
            int gn = n0 + tx + 16 * j;
            if (gn >= Nout) continue;
            float v = acc[i][j] + bias[gn];
            if (EPI == 1) v += res[(size_t)gm * Nout + gn];
            if (EPI == 2) v = 0.5f * v * (1.f + erff(v * 0.70710678118654752f));
            Cout[(size_t)gm * Nout + gn] = v;
        }
    }
}

// ---------------- LayerNorm (one block / row, C=384, 128 thr) ----------------
__global__ __launch_bounds__(128)
void ln_kernel(const float* __restrict__ x, const float* __restrict__ g,
               const float* __restrict__ bb, float* __restrict__ y) {
    size_t row = blockIdx.x;
    const float* xr = x + row * CDIM;
    int t = threadIdx.x;
    float v[3];
    float s = 0.f, s2 = 0.f;
#pragma unroll
    for (int l = 0; l < 3; l++) { v[l] = xr[t + 128 * l]; s += v[l]; s2 += v[l] * v[l]; }
#pragma unroll
    for (int o = 16; o; o >>= 1) {
        s  += __shfl_xor_sync(~0u, s, o);
        s2 += __shfl_xor_sync(~0u, s2, o);
    }
    __shared__ float ws[4], ws2[4];
    if ((t & 31) == 0) { ws[t >> 5] = s; ws2[t >> 5] = s2; }
    __syncthreads();
    s  = ws[0] + ws[1] + ws[2] + ws[3];
    s2 = ws2[0] + ws2[1] + ws2[2] + ws2[3];
    float mean = s * (1.f / CDIM);
    float var  = s2 * (1.f / CDIM) - mean * mean;
    float r = rsqrtf(var + EPSLN);
    float* yr = y + row * CDIM;
#pragma unroll
    for (int l = 0; l < 3; l++) {
        int c = t + 128 * l;
        yr[c] = (v[l] - mean) * r * g[c] + bb[c];
    }
}

// ---------------- QK^T * scale  (per (b,h): [N,64] x [N,64]^T) ----------------
__global__ __launch_bounds__(256)
void qk_kernel(const float* __restrict__ qkv, float* __restrict__ attn, int N) {
    int bh = blockIdx.z;
    int b  = bh / HEADS, hh = bh % HEADS;
    int i0 = blockIdx.y * 32, j0 = blockIdx.x * 32;
    __shared__ float Qs[32][65];
    __shared__ float Ks[32][65];
    int t = threadIdx.x;
#pragma unroll
    for (int l = 0; l < 8; l++) {
        int idx = t + l * 256;
        int r = idx >> 6, d = idx & 63;
        int gi = i0 + r, gj = j0 + r;
        Qs[r][d] = (gi < N) ? qkv[((size_t)b * N + gi) * 1152 + hh * 64 + d] : 0.f;
        Ks[r][d] = (gj < N) ? qkv[((size_t)b * N + gj) * 1152 + 384 + hh * 64 + d] : 0.f;
    }
    __syncthreads();
    int tx = t & 15, ty = t >> 4;
    float acc[2][2] = {};
#pragma unroll
    for (int d = 0; d < 64; d++) {
        float q0 = Qs[ty][d], q1 = Qs[ty + 16][d];
        float k0 = Ks[tx][d], k1 = Ks[tx + 16][d];
        acc[0][0] += q0 * k0; acc[0][1] += q0 * k1;
        acc[1][0] += q1 * k0; acc[1][1] += q1 * k1;
    }
#pragma unroll
    for (int ii = 0; ii < 2; ii++) {
        int gi = i0 + ty + 16 * ii;
        if (gi >= N) continue;
#pragma unroll
        for (int jj = 0; jj < 2; jj++) {
            int gj = j0 + tx + 16 * jj;
            if (gj >= N) continue;
            attn[((size_t)bh * N + gi) * N + gj] = acc[ii][jj] * SCALE;
        }
    }
}

// ---------------- row softmax ----------------
__global__ __launch_bounds__(128)
void softmax_kernel(float* __restrict__ attn, int N) {
    size_t row = blockIdx.x;
    float* a = attn + row * (size_t)N;
    int t = threadIdx.x;
    __shared__ float red[4];
    float mx = -1e30f;
    for (int j = t; j < N; j += 128) mx = fmaxf(mx, a[j]);
#pragma unroll
    for (int o = 16; o; o >>= 1) mx = fmaxf(mx, __shfl_xor_sync(~0u, mx, o));
    if ((t & 31) == 0) red[t >> 5] = mx;
    __syncthreads();
    mx = fmaxf(fmaxf(red[0], red[1]), fmaxf(red[2], red[3]));
    __syncthreads();
    float sum = 0.f;
    for (int j = t; j < N; j += 128) { float e = expf(a[j] - mx); a[j] = e; sum += e; }
#pragma unroll
    for (int o = 16; o; o >>= 1) sum += __shfl_xor_sync(~0u, sum, o);
    if ((t & 31) == 0) red[t >> 5] = sum;
    __syncthreads();
    sum = red[0] + red[1] + red[2] + red[3];
    float inv = 1.f / sum;
    for (int j = t; j < N; j += 128) a[j] *= inv;
}

// ---------------- attn @ V  -> attnout[B*N, C] (head-interleaved) ----------------
__global__ __launch_bounds__(256)
void av_kernel(const float* __restrict__ attn, const float* __restrict__ qkv,
               float* __restrict__ out, int N) {
    int bh = blockIdx.y;
    int b = bh / HEADS, hh = bh % HEADS;
    int i0 = blockIdx.x * 32;
    __shared__ float Ps[32][33];
    __shared__ float Vs[32][65];
    int t = threadIdx.x;
    int r = t >> 3;      // 0..31
    int dg = t & 7;      // 0..7
    float acc[8] = {};
    for (int j0 = 0; j0 < N; j0 += 32) {
#pragma unroll
        for (int l = 0; l < 4; l++) {
            int idx = t + l * 256;
            int rr = idx >> 5, jj = idx & 31;
            int gi = i0 + rr, gj = j0 + jj;
            Ps[rr][jj] = (gi < N && gj < N) ? attn[((size_t)bh * N + gi) * N + gj] : 0.f;
        }
#pragma unroll
        for (int l = 0; l < 8; l++) {
            int idx = t + l * 256;
            int jj = idx >> 6, d = idx & 63;
            int gj = j0 + jj;
            Vs[jj][d] = (gj < N) ? qkv[((size_t)b * N + gj) * 1152 + 768 + hh * 64 + d] : 0.f;
        }
        __syncthreads();
#pragma unroll
        for (int jj = 0; jj < 32; jj++) {
            float p = Ps[r][jj];
#pragma unroll
            for (int q = 0; q < 8; q++)
                acc[q] += p * Vs[jj][dg + 8 * q];
        }
        __syncthreads();
    }
    int gi = i0 + r;
    if (gi < N) {
#pragma unroll
        for (int q = 0; q < 8; q++)
            out[((size_t)b * N + gi) * CDIM + hh * 64 + dg + 8 * q] = acc[q];
    }
}

// ---------------- prune: head-mean CLS attention scores ----------------
__global__ void scoremean_kernel(const float* __restrict__ attn, float* __restrict__ scores, int N) {
    int Ntok = N - 1;
    int i = blockIdx.x * 256 + threadIdx.x;
    if (i >= BATCH * Ntok) return;
    int b = i / Ntok, j = i % Ntok;
    float s = 0.f;
#pragma unroll
    for (int hh = 0; hh < HEADS; hh++)
        s += attn[((size_t)(b * HEADS + hh) * N) * N + 1 + j];
    scores[i] = s * (1.f / HEADS);
}

// stable descending top-k via O(n^2) rank (n<=196)
__global__ __launch_bounds__(256)
void rank_kernel(const float* __restrict__ scores, int* __restrict__ idxout, int Ntok, int keep) {
    int b = blockIdx.x;
    __shared__ float s[256];
    int t = threadIdx.x;
    if (t < Ntok) s[t] = scores[b * Ntok + t];
    __syncthreads();
    if (t < Ntok) {
        float mine = s[t];
        int r = 0;
        for (int j = 0; j < Ntok; j++)
            r += (s[j] > mine) || (s[j] == mine && j < t);
        if (r < keep) idxout[b * keep + r] = t;
    }
}

__global__ void gather_kernel(const float* __restrict__ src, float* __restrict__ dst,
                              const int* __restrict__ idx, int N, int keep) {
    int newN = keep + 1;
    size_t TOT = (size_t)BATCH * newN * CDIM;
    size_t i = (size_t)blockIdx.x * 256 + threadIdx.x;
    if (i >= TOT) return;
    int c = i % CDIM;
    int r = (i / CDIM) % newN;
    int b = i / ((size_t)CDIM * newN);
    int sr = (r == 0) ? 0 : 1 + idx[b * keep + r - 1];
    dst[i] = src[((size_t)b * N + sr) * CDIM + c];
}

// ---------------- fused final LN (cls rows) + classification head ----------------
__global__ __launch_bounds__(128)
void head_kernel(const float* __restrict__ h, const float* __restrict__ g,
                 const float* __restrict__ bb, const float* __restrict__ W,
                 const float* __restrict__ wb, float* __restrict__ out, int N) {
    int b = blockIdx.x;
    const float* xr = h + (size_t)(b * N) * CDIM;
    __shared__ float sm[CDIM];
    int t = threadIdx.x;
    float v[3];
    float s = 0.f, s2 = 0.f;
#pragma unroll
    for (int l = 0; l < 3; l++) { v[l] = xr[t + 128 * l]; s += v[l]; s2 += v[l] * v[l]; }
#pragma unroll
    for (int o = 16; o; o >>= 1) {
        s  += __shfl_xor_sync(~0u, s, o);
        s2 += __shfl_xor_sync(~0u, s2, o);
    }
    __shared__ float ws[4], ws2[4];
    if ((t & 31) == 0) { ws[t >> 5] = s; ws2[t >> 5] = s2; }
    __syncthreads();
    s  = ws[0] + ws[1] + ws[2] + ws[3];
    s2 = ws2[0] + ws2[1] + ws2[2] + ws2[3];
    float mean = s * (1.f / CDIM);
    float var  = s2 * (1.f / CDIM) - mean * mean;
    float r = rsqrtf(var + EPSLN);
#pragma unroll
    for (int l = 0; l < 3; l++) {
        int c = t + 128 * l;
        sm[c] = (v[l] - mean) * r * g[c] + bb[c];
    }
    __syncthreads();
    if (t < NCLS) {
        float acc = wb[t];
        for (int k = 0; k < CDIM; k++)
            acc += sm[k] * W[k * NCLS + t];
        out[b * NCLS + t] = acc;
    }
}

// ---------------- launch ----------------
extern "C" void kernel_launch(void* const* d_in, const int* in_sizes, int n_in,
                              void* d_out, int out_size) {
    const float* x        = (const float*)d_in[0];
    const float* patch_w  = (const float*)d_in[1];
    const float* patch_b  = (const float*)d_in[2];
    const float* cls_tok  = (const float*)d_in[3];
    const float* pos_emb  = (const float*)d_in[4];
    const float* ln1_g    = (const float*)d_in[5];
    const float* ln1_b    = (const float*)d_in[6];
    const float* qkv_w    = (const float*)d_in[7];
    const float* qkv_b    = (const float*)d_in[8];
    const float* proj_w   = (const float*)d_in[9];
    const float* proj_b   = (const float*)d_in[10];
    const float* ln2_g    = (const float*)d_in[11];
    const float* ln2_b    = (const float*)d_in[12];
    const float* fc1_w    = (const float*)d_in[13];
    const float* fc1_b    = (const float*)d_in[14];
    const float* fc2_w    = (const float*)d_in[15];
    const float* fc2_b    = (const float*)d_in[16];
    const float* norm_g   = (const float*)d_in[17];
    const float* norm_b   = (const float*)d_in[18];
    const float* head_w   = (const float*)d_in[19];
    const float* head_b   = (const float*)d_in[20];

    float *h[2], *lnb, *qkvb, *attnb, *aob, *mlpb, *patchb, *scoresb;
    int* idxb;
    cudaGetSymbolAddress((void**)&h[0], g_h0);
    cudaGetSymbolAddress((void**)&h[1], g_h1);
    cudaGetSymbolAddress((void**)&lnb, g_ln);
    cudaGetSymbolAddress((void**)&qkvb, g_qkv);
    cudaGetSymbolAddress((void**)&attnb, g_attn);
    cudaGetSymbolAddress((void**)&aob, g_ao);
    cudaGetSymbolAddress((void**)&mlpb, g_mlp);
    cudaGetSymbolAddress((void**)&patchb, g_patch);
    cudaGetSymbolAddress((void**)&scoresb, g_scores);
    cudaGetSymbolAddress((void**)&idxb, g_idx);

    // patch embed
    {
        int tot = BATCH * NPATCH * 768;
        patchify_kernel<<<(tot + 255) / 256, 256>>>(x, patchb);
        int M = BATCH * NPATCH;
        gemm_kernel<0><<<dim3(CDIM / 64, (M + 63) / 64), 256>>>(
            patchb, patch_w, patch_b, nullptr, mlpb, M, 768, CDIM);
        int tot2 = BATCH * MAXN * CDIM;
        assemble_kernel<<<(tot2 + 255) / 256, 256>>>(mlpb, cls_tok, pos_emb, h[0]);
    }

    int cur = 0;
    int N = MAXN;
    for (int l = 0; l < LAYERS; l++) {
        int M = BATCH * N;
        // attention
        ln_kernel<<<M, 128>>>(h[cur], ln1_g + l * CDIM, ln1_b + l * CDIM, lnb);
        gemm_kernel<0><<<dim3(3 * CDIM / 64, (M + 63) / 64), 256>>>(
            lnb, qkv_w + (size_t)l * CDIM * 3 * CDIM, qkv_b + l * 3 * CDIM,
            nullptr, qkvb, M, CDIM, 3 * CDIM);
        int nt = (N + 31) / 32;
        qk_kernel<<<dim3(nt, nt, BATCH * HEADS), 256>>>(qkvb, attnb, N);
        softmax_kernel<<<BATCH * HEADS * N, 128>>>(attnb, N);
        av_kernel<<<dim3(nt, BATCH * HEADS), 256>>>(attnb, qkvb, aob, N);
        gemm_kernel<1><<<dim3(CDIM / 64, (M + 63) / 64), 256>>>(
            aob, proj_w + (size_t)l * CDIM * CDIM, proj_b + l * CDIM,
            h[cur], h[cur], M, CDIM, CDIM);
        // prune
        if (l == 2 || l == 4 || l == 6) {
            int keep = (l == 2) ? 176 : (l == 4) ? 149 : 119;
            int Ntok = N - 1;
            scoremean_kernel<<<(BATCH * Ntok + 255) / 256, 256>>>(attnb, scoresb, N);
            rank_kernel<<<BATCH, 256>>>(scoresb, idxb, Ntok, keep);
            int newN = keep + 1;
            size_t tot = (size_t)BATCH * newN * CDIM;
            gather_kernel<<<(int)((tot + 255) / 256), 256>>>(h[cur], h[1 - cur], idxb, N, keep);
            cur ^= 1;
            N = newN;
            M = BATCH * N;
        }
        // mlp
        ln_kernel<<<M, 128>>>(h[cur], ln2_g + l * CDIM, ln2_b + l * CDIM, lnb);
        gemm_kernel<2><<<dim3(MLPD / 64, (M + 63) / 64), 256>>>(
            lnb, fc1_w + (size_t)l * CDIM * MLPD, fc1_b + l * MLPD,
            nullptr, mlpb, M, CDIM, MLPD);
        gemm_kernel<1><<<dim3(CDIM / 64, (M + 63) / 64), 256>>>(
            mlpb, fc2_w + (size_t)l * MLPD * CDIM, fc2_b + l * CDIM,
            h[cur], h[cur], M, MLPD, CDIM);
    }

    head_kernel<<<BATCH, 128>>>(h[cur], norm_g, norm_b, head_w, head_b, (float*)d_out, N);
}

// round 2
// speedup vs baseline: 1.6916x; 1.6916x over previous
#include <cuda_runtime.h>
#include <cuda_bf16.h>
#include <math.h>

// ---------------- problem constants ----------------
#define BATCH   64
#define CDIM    384
#define HEADS   6
#define HD      64
#define MLPD    1536
#define LAYERS  12
#define NPATCH  196
#define MAXN    197
#define NCLS    100
#define EPSLN   1e-6f
#define SCALE   0.125f   // 64^-0.5
#define ASTRIDE 224      // padded attn row stride (>= ceil(197/64)*64 would be 256; av reads <=224)

// ---------------- device scratch (no cudaMalloc allowed) ----------------
__device__ float g_h0[(size_t)BATCH * MAXN * CDIM];
__device__ float g_h1[(size_t)BATCH * MAXN * CDIM];
__device__ float g_ln[(size_t)BATCH * MAXN * CDIM];
__device__ float g_qkv[(size_t)BATCH * MAXN * 3 * CDIM];
__device__ float g_attn[(size_t)BATCH * HEADS * MAXN * ASTRIDE];
__device__ float g_ao[(size_t)BATCH * MAXN * CDIM];
__device__ float g_mlp[(size_t)BATCH * MAXN * MLPD];
__device__ float g_patch[(size_t)BATCH * NPATCH * 768];
__device__ float g_scores[BATCH * NPATCH];
__device__ int   g_idx[BATCH * NPATCH];

// ---------------- tf32 split helpers ----------------
__device__ __forceinline__ void split_tf32(float x, unsigned& hi, unsigned& lo) {
    unsigned h;
    asm("cvt.rna.tf32.f32 %0, %1;" : "=r"(h) : "f"(x));
    float r = x - __uint_as_float(h);
    unsigned l;
    asm("cvt.rna.tf32.f32 %0, %1;" : "=r"(l) : "f"(r));
    hi = h; lo = l;
}

__device__ __forceinline__ void mma8(float* c, const unsigned* a, const unsigned* b) {
    asm volatile(
        "mma.sync.aligned.m16n8k8.row.col.f32.tf32.tf32.f32 "
        "{%0,%1,%2,%3}, {%4,%5,%6,%7}, {%8,%9}, {%0,%1,%2,%3};"
        : "+f"(c[0]), "+f"(c[1]), "+f"(c[2]), "+f"(c[3])
        : "r"(a[0]), "r"(a[1]), "r"(a[2]), "r"(a[3]), "r"(b[0]), "r"(b[1]));
}

// ---------------- patchify: x[B,3,224,224] -> p[B,196,768] ----------------
__global__ void patchify_kernel(const float* __restrict__ x, float* __restrict__ p) {
    int i = blockIdx.x * 256 + threadIdx.x;
    const int TOT = BATCH * NPATCH * 768;
    if (i >= TOT) return;
    int k  = i % 768;
    int tt = (i / 768) % NPATCH;
    int b  = i / (768 * NPATCH);
    int ch = k >> 8;
    int py = (k >> 4) & 15;
    int px = k & 15;
    int gy = tt / 14, gx = tt % 14;
    p[i] = x[(((size_t)b * 3 + ch) * 224 + gy * 16 + py) * 224 + gx * 16 + px];
}

// ---------------- assemble: cls + patch-embed + pos ----------------
__global__ void assemble_kernel(const float* __restrict__ pe, const float* __restrict__ cls,
                                const float* __restrict__ pos, float* __restrict__ h) {
    int i = blockIdx.x * 256 + threadIdx.x;
    const int TOT = BATCH * MAXN * CDIM;
    if (i >= TOT) return;
    int c = i % CDIM;
    int r = (i / CDIM) % MAXN;
    int b = i / (CDIM * MAXN);
    float v = (r == 0) ? cls[c] : pe[((size_t)b * NPATCH + (r - 1)) * CDIM + c];
    h[i] = v + pos[r * CDIM + c];
}

// ---------------- split-tf32 GEMM: C = A[M,K] @ W[K,N] + bias (+res | gelu) ----
// tile 128x64, 256 threads (8 warps = 4x2), warp tile 32x32, K chunk 32.
// EPI: 0 = bias, 1 = bias + residual, 2 = bias + exact GELU
template<int EPI>
__global__ __launch_bounds__(256, 2)
void gemm_tf32(const float* __restrict__ A, const float* __restrict__ W,
               const float* __restrict__ bias, const float* __restrict__ res,
               float* __restrict__ Cout, int M, int K, int Nout) {
    __shared__ __align__(16) float As[128][36];
    __shared__ __align__(16) float Bs[32][72];
    int m0 = blockIdx.y * 128;
    int n0 = blockIdx.x * 64;
    int t  = threadIdx.x;
    int lane = t & 31, wid = t >> 5;
    int g = lane >> 2, q = lane & 3;
    int warp_m = wid >> 1, warp_n = wid & 1;

    float acc[2][4][4] = {};

    for (int k0 = 0; k0 < K; k0 += 32) {
        // load A tile 128x32 (float4 along K)
#pragma unroll
        for (int it = 0; it < 4; it++) {
            int idx = t + it * 256;
            int row = idx >> 3, c4 = idx & 7;
            int gm = m0 + row;
            float4 v = make_float4(0.f, 0.f, 0.f, 0.f);
            if (gm < M) v = *reinterpret_cast<const float4*>(&A[(size_t)gm * K + k0 + 4 * c4]);
            *reinterpret_cast<float4*>(&As[row][4 * c4]) = v;
        }
        // load B tile 32x64 (float4 along N)
#pragma unroll
        for (int it = 0; it < 2; it++) {
            int idx = t + it * 256;
            int kk = idx >> 4, n4 = idx & 15;
            float4 v = *reinterpret_cast<const float4*>(&W[(size_t)(k0 + kk) * Nout + n0 + 4 * n4]);
            *reinterpret_cast<float4*>(&Bs[kk][4 * n4]) = v;
        }
        __syncthreads();
#pragma unroll
        for (int ks = 0; ks < 4; ks++) {
            int kb = ks * 8;
            unsigned ah[2][4], al[2][4];
#pragma unroll
            for (int tm = 0; tm < 2; tm++) {
                int r = warp_m * 32 + tm * 16 + g;
                split_tf32(As[r][kb + q],         ah[tm][0], al[tm][0]);
                split_tf32(As[r + 8][kb + q],     ah[tm][1], al[tm][1]);
                split_tf32(As[r][kb + 4 + q],     ah[tm][2], al[tm][2]);
                split_tf32(As[r + 8][kb + 4 + q], ah[tm][3], al[tm][3]);
            }
            unsigned bh[4][2], bl[4][2];
#pragma unroll
            for (int tn = 0; tn < 4; tn++) {
                int n = warp_n * 32 + tn * 8 + g;
                split_tf32(Bs[kb + q][n],     bh[tn][0], bl[tn][0]);
                split_tf32(Bs[kb + 4 + q][n], bh[tn][1], bl[tn][1]);
            }
#pragma unroll
            for (int tm = 0; tm < 2; tm++)
#pragma unroll
                for (int tn = 0; tn < 4; tn++) {
                    mma8(acc[tm][tn], ah[tm], bh[tn]);
                    mma8(acc[tm][tn], ah[tm], bl[tn]);
                    mma8(acc[tm][tn], al[tm], bh[tn]);
                }
        }
        __syncthreads();
    }

#pragma unroll
    for (int tm = 0; tm < 2; tm++) {
#pragma unroll
        for (int tn = 0; tn < 4; tn++) {
            int col = n0 + warp_n * 32 + tn * 8 + 2 * q;
            int r0 = m0 + warp_m * 32 + tm * 16 + g;
#pragma unroll
            for (int half = 0; half < 2; half++) {
                int gm = r0 + 8 * half;
                if (gm >= M) continue;
#pragma unroll
                for (int cc = 0; cc < 2; cc++) {
                    float v = acc[tm][tn][half * 2 + cc] + bias[col + cc];
                    if (EPI == 1) v += res[(size_t)gm * Nout + col + cc];
                    if (EPI == 2) v = 0.5f * v * (1.f + erff(v * 0.70710678118654752f));
                    Cout[(size_t)gm * Nout + col + cc] = v;
                }
            }
        }
    }
}

// ---------------- LayerNorm (one block / row, C=384, 128 thr) ----------------
__global__ __launch_bounds__(128)
void ln_kernel(const float* __restrict__ x, const float* __restrict__ g,
               const float* __restrict__ bb, float* __restrict__ y) {
    size_t row = blockIdx.x;
    const float* xr = x + row * CDIM;
    int t = threadIdx.x;
    float v[3];
    float s = 0.f, s2 = 0.f;
#pragma unroll
    for (int l = 0; l < 3; l++) { v[l] = xr[t + 128 * l]; s += v[l]; s2 += v[l] * v[l]; }
#pragma unroll
    for (int o = 16; o; o >>= 1) {
        s  += __shfl_xor_sync(~0u, s, o);
        s2 += __shfl_xor_sync(~0u, s2, o);
    }
    __shared__ float ws[4], ws2[4];
    if ((t & 31) == 0) { ws[t >> 5] = s; ws2[t >> 5] = s2; }
    __syncthreads();
    s  = ws[0] + ws[1] + ws[2] + ws[3];
    s2 = ws2[0] + ws2[1] + ws2[2] + ws2[3];
    float mean = s * (1.f / CDIM);
    float var  = s2 * (1.f / CDIM) - mean * mean;
    float r = rsqrtf(var + EPSLN);
    float* yr = y + row * CDIM;
#pragma unroll
    for (int l = 0; l < 3; l++) {
        int c = t + 128 * l;
        yr[c] = (v[l] - mean) * r * g[c] + bb[c];
    }
}

// ---------------- QK^T * scale via split-tf32 mma ----------------
// per (b,h), 64x64 output tile, 4 warps (2x2), K=64 fully staged.
__global__ __launch_bounds__(128)
void qk_tf32(const float* __restrict__ qkv, float* __restrict__ attn, int N) {
    int bh = blockIdx.z;
    int b = bh / HEADS, hh = bh % HEADS;
    int i0 = blockIdx.y * 64, j0 = blockIdx.x * 64;
    __shared__ __align__(16) float Qs[64][68];
    __shared__ __align__(16) float Ks[64][68];
    int t = threadIdx.x;
    int lane = t & 31, wid = t >> 5;
    int g = lane >> 2, q = lane & 3;
    int warp_m = wid >> 1, warp_n = wid & 1;

#pragma unroll
    for (int it = 0; it < 8; it++) {
        int idx = t + it * 128;
        int row = idx >> 4, c4 = idx & 15;
        int gi = i0 + row, gj = j0 + row;
        float4 vq = make_float4(0.f, 0.f, 0.f, 0.f), vk = vq;
        if (gi < N) vq = *reinterpret_cast<const float4*>(&qkv[((size_t)b * N + gi) * 1152 + hh * 64 + 4 * c4]);
        if (gj < N) vk = *reinterpret_cast<const float4*>(&qkv[((size_t)b * N + gj) * 1152 + 384 + hh * 64 + 4 * c4]);
        *reinterpret_cast<float4*>(&Qs[row][4 * c4]) = vq;
        *reinterpret_cast<float4*>(&Ks[row][4 * c4]) = vk;
    }
    __syncthreads();

    float acc[2][4][4] = {};
#pragma unroll
    for (int ks = 0; ks < 8; ks++) {
        int kb = ks * 8;
        unsigned ah[2][4], al[2][4];
#pragma unroll
        for (int tm = 0; tm < 2; tm++) {
            int r = warp_m * 32 + tm * 16 + g;
            split_tf32(Qs[r][kb + q],         ah[tm][0], al[tm][0]);
            split_tf32(Qs[r + 8][kb + q],     ah[tm][1], al[tm][1]);
            split_tf32(Qs[r][kb + 4 + q],     ah[tm][2], al[tm][2]);
            split_tf32(Qs[r + 8][kb + 4 + q], ah[tm][3], al[tm][3]);
        }
        unsigned bh2[4][2], bl2[4][2];
#pragma unroll
        for (int tn = 0; tn < 4; tn++) {
            int n = warp_n * 32 + tn * 8 + g;
            split_tf32(Ks[n][kb + q],     bh2[tn][0], bl2[tn][0]);
            split_tf32(Ks[n][kb + 4 + q], bh2[tn][1], bl2[tn][1]);
        }
#pragma unroll
        for (int tm = 0; tm < 2; tm++)
#pragma unroll
            for (int tn = 0; tn < 4; tn++) {
                mma8(acc[tm][tn], ah[tm], bh2[tn]);
                mma8(acc[tm][tn], ah[tm], bl2[tn]);
                mma8(acc[tm][tn], al[tm], bh2[tn]);
            }
    }

    // write, zero-filling the pad region [N, ASTRIDE)
#pragma unroll
    for (int tm = 0; tm < 2; tm++) {
#pragma unroll
        for (int tn = 0; tn < 4; tn++) {
            int col = j0 + warp_n * 32 + tn * 8 + 2 * q;
            int r0 = i0 + warp_m * 32 + tm * 16 + g;
#pragma unroll
            for (int half = 0; half < 2; half++) {
                int gi = r0 + 8 * half;
                if (gi >= N) continue;
#pragma unroll
                for (int cc = 0; cc < 2; cc++) {
                    int gj = col + cc;
                    if (gj < ASTRIDE)
                        attn[((size_t)bh * N + gi) * ASTRIDE + gj] =
                            (gj < N) ? acc[tm][tn][half * 2 + cc] * SCALE : 0.f;
                }
            }
        }
    }
}

// ---------------- row softmax (stride ASTRIDE) ----------------
__global__ __launch_bounds__(128)
void softmax_kernel(float* __restrict__ attn, int N) {
    size_t row = blockIdx.x;
    float* a = attn + row * ASTRIDE;
    int t = threadIdx.x;
    __shared__ float red[4];
    float mx = -1e30f;
    for (int j = t; j < N; j += 128) mx = fmaxf(mx, a[j]);
#pragma unroll
    for (int o = 16; o; o >>= 1) mx = fmaxf(mx, __shfl_xor_sync(~0u, mx, o));
    if ((t & 31) == 0) red[t >> 5] = mx;
    __syncthreads();
    mx = fmaxf(fmaxf(red[0], red[1]), fmaxf(red[2], red[3]));
    __syncthreads();
    float sum = 0.f;
    for (int j = t; j < N; j += 128) { float e = expf(a[j] - mx); a[j] = e; sum += e; }
#pragma unroll
    for (int o = 16; o; o >>= 1) sum += __shfl_xor_sync(~0u, sum, o);
    if ((t & 31) == 0) red[t >> 5] = sum;
    __syncthreads();
    sum = red[0] + red[1] + red[2] + red[3];
    float inv = 1.f / sum;
    for (int j = t; j < N; j += 128) a[j] *= inv;
}

// ---------------- attn @ V via split-tf32 mma ----------------
// per (b,h): rows tile 64, cols = 64 (full head dim), K chunks of 32 over tokens.
__global__ __launch_bounds__(128)
void av_tf32(const float* __restrict__ attn, const float* __restrict__ qkv,
             float* __restrict__ out, int N) {
    int bh = blockIdx.y;
    int b = bh / HEADS, hh = bh % HEADS;
    int i0 = blockIdx.x * 64;
    __shared__ __align__(16) float Ps[64][36];
    __shared__ __align__(16) float Vs[32][72];
    int t = threadIdx.x;
    int lane = t & 31, wid = t >> 5;
    int g = lane >> 2, q = lane & 3;
    int warp_m = wid >> 1, warp_n = wid & 1;

    float acc[2][4][4] = {};
    int nchunks = (N + 31) / 32;
    for (int c = 0; c < nchunks; c++) {
        int j0 = c * 32;
#pragma unroll
        for (int it = 0; it < 4; it++) {
            int idx = t + it * 128;
            int row = idx >> 3, c4 = idx & 7;
            int gi = i0 + row;
            float4 v = make_float4(0.f, 0.f, 0.f, 0.f);
            if (gi < N) v = *reinterpret_cast<const float4*>(&attn[((size_t)bh * N + gi) * ASTRIDE + j0 + 4 * c4]);
            *reinterpret_cast<float4*>(&Ps[row][4 * c4]) = v;
        }
#pragma unroll
        for (int it = 0; it < 4; it++) {
            int idx = t + it * 128;
            int row = idx >> 4, c4 = idx & 15;
            int gj = j0 + row;
            float4 v = make_float4(0.f, 0.f, 0.f, 0.f);
            if (gj < N) v = *reinterpret_cast<const float4*>(&qkv[((size_t)b * N + gj) * 1152 + 768 + hh * 64 + 4 * c4]);
            *reinterpret_cast<float4*>(&Vs[row][4 * c4]) = v;
        }
        __syncthreads();
#pragma unroll
        for (int ks = 0; ks < 4; ks++) {
            int kb = ks * 8;
            unsigned ah[2][4], al[2][4];
#pragma unroll
            for (int tm = 0; tm < 2; tm++) {
                int r = warp_m * 32 + tm * 16 + g;
                split_tf32(Ps[r][kb + q],         ah[tm][0], al[tm][0]);
                split_tf32(Ps[r + 8][kb + q],     ah[tm][1], al[tm][1]);
                split_tf32(Ps[r][kb + 4 + q],     ah[tm][2], al[tm][2]);
                split_tf32(Ps[r + 8][kb + 4 + q], ah[tm][3], al[tm][3]);
            }
            unsigned bh2[4][2], bl2[4][2];
#pragma unroll
            for (int tn = 0; tn < 4; tn++) {
                int n = warp_n * 32 + tn * 8 + g;
                split_tf32(Vs[kb + q][n],     bh2[tn][0], bl2[tn][0]);
                split_tf32(Vs[kb + 4 + q][n], bh2[tn][1], bl2[tn][1]);
            }
#pragma unroll
            for (int tm = 0; tm < 2; tm++)
#pragma unroll
                for (int tn = 0; tn < 4; tn++) {
                    mma8(acc[tm][tn], ah[tm], bh2[tn]);
                    mma8(acc[tm][tn], ah[tm], bl2[tn]);
                    mma8(acc[tm][tn], al[tm], bh2[tn]);
                }
        }
        __syncthreads();
    }

#pragma unroll
    for (int tm = 0; tm < 2; tm++) {
#pragma unroll
        for (int tn = 0; tn < 4; tn++) {
            int d = warp_n * 32 + tn * 8 + 2 * q;
            int r0 = i0 + warp_m * 32 + tm * 16 + g;
#pragma unroll
            for (int half = 0; half < 2; half++) {
                int gi = r0 + 8 * half;
                if (gi >= N) continue;
                out[((size_t)b * N + gi) * CDIM + hh * 64 + d]     = acc[tm][tn][half * 2];
                out[((size_t)b * N + gi) * CDIM + hh * 64 + d + 1] = acc[tm][tn][half * 2 + 1];
            }
        }
    }
}

// ---------------- prune: head-mean CLS attention scores ----------------
__global__ void scoremean_kernel(const float* __restrict__ attn, float* __restrict__ scores, int N) {
    int Ntok = N - 1;
    int i = blockIdx.x * 256 + threadIdx.x;
    if (i >= BATCH * Ntok) return;
    int b = i / Ntok, j = i % Ntok;
    float s = 0.f;
#pragma unroll
    for (int hh = 0; hh < HEADS; hh++)
        s += attn[((size_t)(b * HEADS + hh) * N) * ASTRIDE + 1 + j];
    scores[i] = s * (1.f / HEADS);
}

// stable descending top-k via O(n^2) rank (n<=196)
__global__ __launch_bounds__(256)
void rank_kernel(const float* __restrict__ scores, int* __restrict__ idxout, int Ntok, int keep) {
    int b = blockIdx.x;
    __shared__ float s[256];
    int t = threadIdx.x;
    if (t < Ntok) s[t] = scores[b * Ntok + t];
    __syncthreads();
    if (t < Ntok) {
        float mine = s[t];
        int r = 0;
        for (int j = 0; j < Ntok; j++)
            r += (s[j] > mine) || (s[j] == mine && j < t);
        if (r < keep) idxout[b * keep + r] = t;
    }
}

__global__ void gather_kernel(const float* __restrict__ src, float* __restrict__ dst,
                              const int* __restrict__ idx, int N, int keep) {
    int newN = keep + 1;
    size_t TOT = (size_t)BATCH * newN * CDIM;
    size_t i = (size_t)blockIdx.x * 256 + threadIdx.x;
    if (i >= TOT) return;
    int c = i % CDIM;
    int r = (i / CDIM) % newN;
    int b = i / ((size_t)CDIM * newN);
    int sr = (r == 0) ? 0 : 1 + idx[b * keep + r - 1];
    dst[i] = src[((size_t)b * N + sr) * CDIM + c];
}

// ---------------- fused final LN (cls rows) + classification head ----------------
__global__ __launch_bounds__(128)
void head_kernel(const float* __restrict__ h, const float* __restrict__ g,
                 const float* __restrict__ bb, const float* __restrict__ W,
                 const float* __restrict__ wb, float* __restrict__ out, int N) {
    int b = blockIdx.x;
    const float* xr = h + (size_t)(b * N) * CDIM;
    __shared__ float sm[CDIM];
    int t = threadIdx.x;
    float v[3];
    float s = 0.f, s2 = 0.f;
#pragma unroll
    for (int l = 0; l < 3; l++) { v[l] = xr[t + 128 * l]; s += v[l]; s2 += v[l] * v[l]; }
#pragma unroll
    for (int o = 16; o; o >>= 1) {
        s  += __shfl_xor_sync(~0u, s, o);
        s2 += __shfl_xor_sync(~0u, s2, o);
    }
    __shared__ float ws[4], ws2[4];
    if ((t & 31) == 0) { ws[t >> 5] = s; ws2[t >> 5] = s2; }
    __syncthreads();
    s  = ws[0] + ws[1] + ws[2] + ws[3];
    s2 = ws2[0] + ws2[1] + ws2[2] + ws2[3];
    float mean = s * (1.f / CDIM);
    float var  = s2 * (1.f / CDIM) - mean * mean;
    float r = rsqrtf(var + EPSLN);
#pragma unroll
    for (int l = 0; l < 3; l++) {
        int c = t + 128 * l;
        sm[c] = (v[l] - mean) * r * g[c] + bb[c];
    }
    __syncthreads();
    if (t < NCLS) {
        float acc = wb[t];
        for (int k = 0; k < CDIM; k++)
            acc += sm[k] * W[k * NCLS + t];
        out[b * NCLS + t] = acc;
    }
}

// ---------------- launch ----------------
extern "C" void kernel_launch(void* const* d_in, const int* in_sizes, int n_in,
                              void* d_out, int out_size) {
    const float* x        = (const float*)d_in[0];
    const float* patch_w  = (const float*)d_in[1];
    const float* patch_b  = (const float*)d_in[2];
    const float* cls_tok  = (const float*)d_in[3];
    const float* pos_emb  = (const float*)d_in[4];
    const float* ln1_g    = (const float*)d_in[5];
    const float* ln1_b    = (const float*)d_in[6];
    const float* qkv_w    = (const float*)d_in[7];
    const float* qkv_b    = (const float*)d_in[8];
    const float* proj_w   = (const float*)d_in[9];
    const float* proj_b   = (const float*)d_in[10];
    const float* ln2_g    = (const float*)d_in[11];
    const float* ln2_b    = (const float*)d_in[12];
    const float* fc1_w    = (const float*)d_in[13];
    const float* fc1_b    = (const float*)d_in[14];
    const float* fc2_w    = (const float*)d_in[15];
    const float* fc2_b    = (const float*)d_in[16];
    const float* norm_g   = (const float*)d_in[17];
    const float* norm_b   = (const float*)d_in[18];
    const float* head_w   = (const float*)d_in[19];
    const float* head_b   = (const float*)d_in[20];

    float *h[2], *lnb, *qkvb, *attnb, *aob, *mlpb, *patchb, *scoresb;
    int* idxb;
    cudaGetSymbolAddress((void**)&h[0], g_h0);
    cudaGetSymbolAddress((void**)&h[1], g_h1);
    cudaGetSymbolAddress((void**)&lnb, g_ln);
    cudaGetSymbolAddress((void**)&qkvb, g_qkv);
    cudaGetSymbolAddress((void**)&attnb, g_attn);
    cudaGetSymbolAddress((void**)&aob, g_ao);
    cudaGetSymbolAddress((void**)&mlpb, g_mlp);
    cudaGetSymbolAddress((void**)&patchb, g_patch);
    cudaGetSymbolAddress((void**)&scoresb, g_scores);
    cudaGetSymbolAddress((void**)&idxb, g_idx);

    // patch embed
    {
        int tot = BATCH * NPATCH * 768;
        patchify_kernel<<<(tot + 255) / 256, 256>>>(x, patchb);
        int M = BATCH * NPATCH;
        gemm_tf32<0><<<dim3(CDIM / 64, (M + 127) / 128), 256>>>(
            patchb, patch_w, patch_b, nullptr, mlpb, M, 768, CDIM);
        int tot2 = BATCH * MAXN * CDIM;
        assemble_kernel<<<(tot2 + 255) / 256, 256>>>(mlpb, cls_tok, pos_emb, h[0]);
    }

    int cur = 0;
    int N = MAXN;
    for (int l = 0; l < LAYERS; l++) {
        int M = BATCH * N;
        // attention
        ln_kernel<<<M, 128>>>(h[cur], ln1_g + l * CDIM, ln1_b + l * CDIM, lnb);
        gemm_tf32<0><<<dim3(3 * CDIM / 64, (M + 127) / 128), 256>>>(
            lnb, qkv_w + (size_t)l * CDIM * 3 * CDIM, qkv_b + l * 3 * CDIM,
            nullptr, qkvb, M, CDIM, 3 * CDIM);
        int nt = (N + 63) / 64;
        qk_tf32<<<dim3(nt, nt, BATCH * HEADS), 128>>>(qkvb, attnb, N);
        softmax_kernel<<<BATCH * HEADS * N, 128>>>(attnb, N);
        av_tf32<<<dim3(nt, BATCH * HEADS), 128>>>(attnb, qkvb, aob, N);
        gemm_tf32<1><<<dim3(CDIM / 64, (M + 127) / 128), 256>>>(
            aob, proj_w + (size_t)l * CDIM * CDIM, proj_b + l * CDIM,
            h[cur], h[cur], M, CDIM, CDIM);
        // prune
        if (l == 2 || l == 4 || l == 6) {
            int keep = (l == 2) ? 176 : (l == 4) ? 149 : 119;
            int Ntok = N - 1;
            scoremean_kernel<<<(BATCH * Ntok + 255) / 256, 256>>>(attnb, scoresb, N);
            rank_kernel<<<BATCH, 256>>>(scoresb, idxb, Ntok, keep);
            int newN = keep + 1;
            size_t tot = (size_t)BATCH * newN * CDIM;
            gather_kernel<<<(int)((tot + 255) / 256), 256>>>(h[cur], h[1 - cur], idxb, N, keep);
            cur ^= 1;
            N = newN;
            M = BATCH * N;
        }
        // mlp
        ln_kernel<<<M, 128>>>(h[cur], ln2_g + l * CDIM, ln2_b + l * CDIM, lnb);
        gemm_tf32<2><<<dim3(MLPD / 64, (M + 127) / 128), 256>>>(
            lnb, fc1_w + (size_t)l * CDIM * MLPD, fc1_b + l * MLPD,
            nullptr, mlpb, M, CDIM, MLPD);
        gemm_tf32<1><<<dim3(CDIM / 64, (M + 127) / 128), 256>>>(
            mlpb, fc2_w + (size_t)l * MLPD * CDIM, fc2_b + l * CDIM,
            h[cur], h[cur], M, MLPD, CDIM);
    }

    head_kernel<<<BATCH, 128>>>(h[cur], norm_g, norm_b, head_w, head_b, (float*)d_out, N);
}

// round 3
// speedup vs baseline: 2.0638x; 1.2201x over previous
#include <cuda_runtime.h>
#include <cuda_fp16.h>
#include <math.h>

// ---------------- problem constants ----------------
#define BATCH   64
#define CDIM    384
#define HEADS   6
#define MLPD    1536
#define LAYERS  12
#define NPATCH  196
#define MAXN    197
#define NCLS    100
#define EPSLN   1e-6f
#define SCALE   0.125f
#define ASTRIDE 224
#define WSCALE     64.f
#define INV_WSCALE (1.f/64.f)
#define PSCALE     256.f
#define INV_PSCALE (1.f/256.f)

// transposed-weight half array offsets
#define SZ_PATCH (768*384)
#define SZ_QKV   (384*1152)
#define SZ_PROJ  (384*384)
#define SZ_FC1   (384*1536)
#define SZ_FC2   (1536*384)
#define OFF_PATCH 0
#define OFF_QKV   (SZ_PATCH)
#define OFF_PROJ  (OFF_QKV + 12*SZ_QKV)
#define OFF_FC1   (OFF_PROJ + 12*SZ_PROJ)
#define OFF_FC2   (OFF_FC1 + 12*SZ_FC1)
#define WTOTAL    (OFF_FC2 + 12*SZ_FC2)

// ---------------- device scratch ----------------
__device__ float  g_h0[(size_t)BATCH * MAXN * CDIM];
__device__ float  g_h1[(size_t)BATCH * MAXN * CDIM];
__device__ float  g_attn[(size_t)BATCH * HEADS * MAXN * ASTRIDE];
__device__ float  g_pembed[(size_t)BATCH * NPATCH * CDIM];
__device__ float  g_scores[BATCH * NPATCH];
__device__ int    g_idx[BATCH * NPATCH];

__device__ __half g_wth[(size_t)WTOTAL];
__device__ __half g_wtl[(size_t)WTOTAL];
__device__ __half g_lnh[(size_t)BATCH * MAXN * CDIM];
__device__ __half g_lnl[(size_t)BATCH * MAXN * CDIM];
__device__ __half g_qkvh[(size_t)BATCH * MAXN * 1152];
__device__ __half g_qkvl[(size_t)BATCH * MAXN * 1152];
__device__ __half g_vth[(size_t)BATCH * HEADS * 64 * ASTRIDE];
__device__ __half g_vtl[(size_t)BATCH * HEADS * 64 * ASTRIDE];
__device__ __half g_ph[(size_t)BATCH * HEADS * MAXN * ASTRIDE];
__device__ __half g_pl[(size_t)BATCH * HEADS * MAXN * ASTRIDE];
__device__ __half g_aoh[(size_t)BATCH * MAXN * CDIM];
__device__ __half g_aol[(size_t)BATCH * MAXN * CDIM];
__device__ __half g_mlph[(size_t)BATCH * MAXN * MLPD];
__device__ __half g_mlpl[(size_t)BATCH * MAXN * MLPD];
__device__ __half g_pxh[(size_t)BATCH * NPATCH * 768];
__device__ __half g_pxl[(size_t)BATCH * NPATCH * 768];

// ---------------- helpers ----------------
__device__ __forceinline__ void split_h(float v, __half& h, __half& l) {
    h = __float2half_rn(v);
    l = __float2half_rn(v - __half2float(h));
}

__device__ __forceinline__ void mma16(float* c, const unsigned* a, const unsigned* b) {
    asm volatile(
        "mma.sync.aligned.m16n8k16.row.col.f32.f16.f16.f32 "
        "{%0,%1,%2,%3},{%4,%5,%6,%7},{%8,%9},{%0,%1,%2,%3};"
        : "+f"(c[0]), "+f"(c[1]), "+f"(c[2]), "+f"(c[3])
        : "r"(a[0]), "r"(a[1]), "r"(a[2]), "r"(a[3]), "r"(b[0]), "r"(b[1]));
}

// ---------------- weight transpose + split:  Wt[n][k] = W[k][n] * 64 ----------------
__global__ void wsplit_kernel(const float* __restrict__ W, size_t in_lstride,
                              __half* __restrict__ oh, __half* __restrict__ ol,
                              size_t out_lstride, int K, int N) {
    __shared__ float tile[32][33];
    int k0 = blockIdx.x * 32, n0 = blockIdx.y * 32;
    const float* Wl = W + (size_t)blockIdx.z * in_lstride;
    __half* ohl = oh + (size_t)blockIdx.z * out_lstride;
    __half* oll = ol + (size_t)blockIdx.z * out_lstride;
    int tx = threadIdx.x, ty = threadIdx.y;
#pragma unroll
    for (int i = 0; i < 4; i++)
        tile[ty + 8 * i][tx] = Wl[(size_t)(k0 + ty + 8 * i) * N + n0 + tx];
    __syncthreads();
#pragma unroll
    for (int i = 0; i < 4; i++) {
        int n = n0 + ty + 8 * i, k = k0 + tx;
        float v = tile[tx][ty + 8 * i] * WSCALE;
        __half h, l;
        split_h(v, h, l);
        ohl[(size_t)n * K + k] = h;
        oll[(size_t)n * K + k] = l;
    }
}

// ---------------- patchify + split ----------------
__global__ void patchify_kernel(const float* __restrict__ x,
                                __half* __restrict__ ph, __half* __restrict__ pl) {
    int i = blockIdx.x * 256 + threadIdx.x;
    const int TOT = BATCH * NPATCH * 768;
    if (i >= TOT) return;
    int k  = i % 768;
    int tt = (i / 768) % NPATCH;
    int b  = i / (768 * NPATCH);
    int ch = k >> 8, py = (k >> 4) & 15, px = k & 15;
    int gy = tt / 14, gx = tt % 14;
    float v = x[(((size_t)b * 3 + ch) * 224 + gy * 16 + py) * 224 + gx * 16 + px];
    split_h(v, ph[i], pl[i]);
}

// ---------------- assemble: cls + patch-embed + pos ----------------
__global__ void assemble_kernel(const float* __restrict__ pe, const float* __restrict__ cls,
                                const float* __restrict__ pos, float* __restrict__ h) {
    int i = blockIdx.x * 256 + threadIdx.x;
    const int TOT = BATCH * MAXN * CDIM;
    if (i >= TOT) return;
    int c = i % CDIM;
    int r = (i / CDIM) % MAXN;
    int b = i / (CDIM * MAXN);
    float v = (r == 0) ? cls[c] : pe[((size_t)b * NPATCH + (r - 1)) * CDIM + c];
    h[i] = v + pos[r * CDIM + c];
}

// ---------------- fp16x2 GEMM: C = A[M,K] @ Wt^T + bias;  A,Wt pre-split halves ------
// tile 128x64, 256 thr (8 warps 4x2), warp 32x32, k-chunk 32 (2 x k16 mma steps)
// EPI: 0 bias, 1 bias+res, 2 bias+gelu.  oscale applied to acc before bias.
template<int EPI, bool OF32, bool OHALF>
__global__ __launch_bounds__(256, 2)
void gemm_fp16(const __half* __restrict__ Ah, const __half* __restrict__ Al,
               const __half* __restrict__ Bth, const __half* __restrict__ Btl,
               const float* __restrict__ bias, const float* __restrict__ res,
               float* __restrict__ C32, __half* __restrict__ Ch, __half* __restrict__ Cl,
               int M, int K, int Nout, float oscale) {
    __shared__ __align__(16) __half As[2][128][40];
    __shared__ __align__(16) __half Bs[2][64][40];
    int m0 = blockIdx.y * 128, n0 = blockIdx.x * 64;
    int t = threadIdx.x, lane = t & 31, wid = t >> 5;
    int g = lane >> 2, q = lane & 3;
    int wm = wid >> 1, wn = wid & 1;
    float acc[2][4][4] = {};
    const uint4 z4 = make_uint4(0, 0, 0, 0);

    for (int k0 = 0; k0 < K; k0 += 32) {
#pragma unroll
        for (int s = 0; s < 2; s++) {
            const __half* src = s ? Al : Ah;
#pragma unroll
            for (int it = 0; it < 2; it++) {
                int idx = t + it * 256;
                int row = idx >> 2, c = idx & 3;
                int gm = m0 + row;
                uint4 v = z4;
                if (gm < M) v = *(const uint4*)&src[(size_t)gm * K + k0 + 8 * c];
                *(uint4*)&As[s][row][8 * c] = v;
            }
        }
#pragma unroll
        for (int s = 0; s < 2; s++) {
            const __half* src = s ? Btl : Bth;
            int row = t >> 2, c = t & 3;
            uint4 v = *(const uint4*)&src[(size_t)(n0 + row) * K + k0 + 8 * c];
            *(uint4*)&Bs[s][row][8 * c] = v;
        }
        __syncthreads();
#pragma unroll
        for (int ks = 0; ks < 2; ks++) {
            int kb = ks * 16;
            unsigned aH[2][4], aL[2][4];
#pragma unroll
            for (int tm = 0; tm < 2; tm++) {
                int r0 = wm * 32 + tm * 16;
                aH[tm][0] = *(const unsigned*)&As[0][r0 + g][kb + 2 * q];
                aH[tm][1] = *(const unsigned*)&As[0][r0 + g + 8][kb + 2 * q];
                aH[tm][2] = *(const unsigned*)&As[0][r0 + g][kb + 2 * q + 8];
                aH[tm][3] = *(const unsigned*)&As[0][r0 + g + 8][kb + 2 * q + 8];
                aL[tm][0] = *(const unsigned*)&As[1][r0 + g][kb + 2 * q];
                aL[tm][1] = *(const unsigned*)&As[1][r0 + g + 8][kb + 2 * q];
                aL[tm][2] = *(const unsigned*)&As[1][r0 + g][kb + 2 * q + 8];
                aL[tm][3] = *(const unsigned*)&As[1][r0 + g + 8][kb + 2 * q + 8];
            }
            unsigned bH[4][2], bL[4][2];
#pragma unroll
            for (int tn = 0; tn < 4; tn++) {
                int n = wn * 32 + tn * 8 + g;
                bH[tn][0] = *(const unsigned*)&Bs[0][n][kb + 2 * q];
                bH[tn][1] = *(const unsigned*)&Bs[0][n][kb + 2 * q + 8];
                bL[tn][0] = *(const unsigned*)&Bs[1][n][kb + 2 * q];
                bL[tn][1] = *(const unsigned*)&Bs[1][n][kb + 2 * q + 8];
            }
#pragma unroll
            for (int tm = 0; tm < 2; tm++)
#pragma unroll
                for (int tn = 0; tn < 4; tn++) {
                    mma16(acc[tm][tn], aH[tm], bH[tn]);
                    mma16(acc[tm][tn], aH[tm], bL[tn]);
                    mma16(acc[tm][tn], aL[tm], bH[tn]);
                }
        }
        __syncthreads();
    }

#pragma unroll
    for (int tm = 0; tm < 2; tm++) {
#pragma unroll
        for (int tn = 0; tn < 4; tn++) {
            int col = n0 + wn * 32 + tn * 8 + 2 * q;
            int r0 = m0 + wm * 32 + tm * 16;
#pragma unroll
            for (int hf = 0; hf < 2; hf++) {
                int gm = r0 + g + 8 * hf;
                if (gm >= M) continue;
#pragma unroll
                for (int cc = 0; cc < 2; cc++) {
                    float v = acc[tm][tn][hf * 2 + cc] * oscale + bias[col + cc];
                    if (EPI == 1) v += res[(size_t)gm * Nout + col + cc];
                    if (EPI == 2) v = 0.5f * v * (1.f + erff(v * 0.70710678118654752f));
                    if (OF32) C32[(size_t)gm * Nout + col + cc] = v;
                    if (OHALF) {
                        __half h, l;
                        split_h(v, h, l);
                        Ch[(size_t)gm * Nout + col + cc] = h;
                        Cl[(size_t)gm * Nout + col + cc] = l;
                    }
                }
            }
        }
    }
}

// ---------------- LayerNorm -> split halves ----------------
__global__ __launch_bounds__(128)
void ln_kernel(const float* __restrict__ x, const float* __restrict__ g,
               const float* __restrict__ bb, __half* __restrict__ yh, __half* __restrict__ yl) {
    size_t row = blockIdx.x;
    const float* xr = x + row * CDIM;
    int t = threadIdx.x;
    float v[3];
    float s = 0.f, s2 = 0.f;
#pragma unroll
    for (int l = 0; l < 3; l++) { v[l] = xr[t + 128 * l]; s += v[l]; s2 += v[l] * v[l]; }
#pragma unroll
    for (int o = 16; o; o >>= 1) {
        s  += __shfl_xor_sync(~0u, s, o);
        s2 += __shfl_xor_sync(~0u, s2, o);
    }
    __shared__ float ws[4], ws2[4];
    if ((t & 31) == 0) { ws[t >> 5] = s; ws2[t >> 5] = s2; }
    __syncthreads();
    s  = ws[0] + ws[1] + ws[2] + ws[3];
    s2 = ws2[0] + ws2[1] + ws2[2] + ws2[3];
    float mean = s * (1.f / CDIM);
    float var  = s2 * (1.f / CDIM) - mean * mean;
    float r = rsqrtf(var + EPSLN);
#pragma unroll
    for (int l = 0; l < 3; l++) {
        int c = t + 128 * l;
        float o = (v[l] - mean) * r * g[c] + bb[c];
        split_h(o, yh[row * CDIM + c], yl[row * CDIM + c]);
    }
}

// ---------------- QK^T via fp16x2 mma; writes f32 logits*SCALE ----------------
__global__ __launch_bounds__(128)
void qk_fp16(const __half* __restrict__ qh, const __half* __restrict__ ql,
             float* __restrict__ attn, int N) {
    int bh = blockIdx.z;
    int b = bh / HEADS, hh = bh % HEADS;
    int i0 = blockIdx.y * 64, j0 = blockIdx.x * 64;
    __shared__ __align__(16) __half Qs[2][64][72];
    __shared__ __align__(16) __half Ks[2][64][72];
    int t = threadIdx.x, lane = t & 31, wid = t >> 5;
    int g = lane >> 2, q = lane & 3;
    int wm = wid >> 1, wn = wid & 1;
    const uint4 z4 = make_uint4(0, 0, 0, 0);

#pragma unroll
    for (int s = 0; s < 2; s++) {
        const __half* src = s ? ql : qh;
#pragma unroll
        for (int it = 0; it < 4; it++) {
            int idx = t + it * 128;
            int row = idx >> 3, c = idx & 7;
            int gi = i0 + row, gj = j0 + row;
            uint4 vq = z4, vk = z4;
            if (gi < N) vq = *(const uint4*)&src[((size_t)b * N + gi) * 1152 + hh * 64 + 8 * c];
            if (gj < N) vk = *(const uint4*)&src[((size_t)b * N + gj) * 1152 + 384 + hh * 64 + 8 * c];
            *(uint4*)&Qs[s][row][8 * c] = vq;
            *(uint4*)&Ks[s][row][8 * c] = vk;
        }
    }
    __syncthreads();

    float acc[2][4][4] = {};
#pragma unroll
    for (int ks = 0; ks < 4; ks++) {
        int kb = ks * 16;
        unsigned aH[2][4], aL[2][4];
#pragma unroll
        for (int tm = 0; tm < 2; tm++) {
            int r0 = wm * 32 + tm * 16;
            aH[tm][0] = *(const unsigned*)&Qs[0][r0 + g][kb + 2 * q];
            aH[tm][1] = *(const unsigned*)&Qs[0][r0 + g + 8][kb + 2 * q];
            aH[tm][2] = *(const unsigned*)&Qs[0][r0 + g][kb + 2 * q + 8];
            aH[tm][3] = *(const unsigned*)&Qs[0][r0 + g + 8][kb + 2 * q + 8];
            aL[tm][0] = *(const unsigned*)&Qs[1][r0 + g][kb + 2 * q];
            aL[tm][1] = *(const unsigned*)&Qs[1][r0 + g + 8][kb + 2 * q];
            aL[tm][2] = *(const unsigned*)&Qs[1][r0 + g][kb + 2 * q + 8];
            aL[tm][3] = *(const unsigned*)&Qs[1][r0 + g + 8][kb + 2 * q + 8];
        }
        unsigned bH[4][2], bL[4][2];
#pragma unroll
        for (int tn = 0; tn < 4; tn++) {
            int n = wn * 32 + tn * 8 + g;
            bH[tn][0] = *(const unsigned*)&Ks[0][n][kb + 2 * q];
            bH[tn][1] = *(const unsigned*)&Ks[0][n][kb + 2 * q + 8];
            bL[tn][0] = *(const unsigned*)&Ks[1][n][kb + 2 * q];
            bL[tn][1] = *(const unsigned*)&Ks[1][n][kb + 2 * q + 8];
        }
#pragma unroll
        for (int tm = 0; tm < 2; tm++)
#pragma unroll
            for (int tn = 0; tn < 4; tn++) {
                mma16(acc[tm][tn], aH[tm], bH[tn]);
                mma16(acc[tm][tn], aH[tm], bL[tn]);
                mma16(acc[tm][tn], aL[tm], bH[tn]);
            }
    }

#pragma unroll
    for (int tm = 0; tm < 2; tm++) {
#pragma unroll
        for (int tn = 0; tn < 4; tn++) {
            int col = j0 + wn * 32 + tn * 8 + 2 * q;
            int r0 = i0 + wm * 32 + tm * 16;
#pragma unroll
            for (int hf = 0; hf < 2; hf++) {
                int gi = r0 + g + 8 * hf;
                if (gi >= N) continue;
#pragma unroll
                for (int cc = 0; cc < 2; cc++) {
                    int gj = col + cc;
                    if (gj < N)
                        attn[((size_t)bh * N + gi) * ASTRIDE + gj] = acc[tm][tn][hf * 2 + cc] * SCALE;
                }
            }
        }
    }
}

// ---------------- softmax -> split halves (x256), zero-pad to ASTRIDE ----------------
__global__ __launch_bounds__(128)
void softmax_fp16(const float* __restrict__ attn, __half* __restrict__ Ph,
                  __half* __restrict__ Pl, int N) {
    size_t row = blockIdx.x;
    const float* a = attn + row * ASTRIDE;
    int t = threadIdx.x;
    __shared__ float red[4];
    int j0 = t, j1 = t + 128;
    float x0 = (j0 < N) ? a[j0] : -1e30f;
    float x1 = (j1 < N) ? a[j1] : -1e30f;
    float mx = fmaxf(x0, x1);
#pragma unroll
    for (int o = 16; o; o >>= 1) mx = fmaxf(mx, __shfl_xor_sync(~0u, mx, o));
    if ((t & 31) == 0) red[t >> 5] = mx;
    __syncthreads();
    mx = fmaxf(fmaxf(red[0], red[1]), fmaxf(red[2], red[3]));
    __syncthreads();
    float e0 = (j0 < N) ? expf(x0 - mx) : 0.f;
    float e1 = (j1 < N) ? expf(x1 - mx) : 0.f;
    float sum = e0 + e1;
#pragma unroll
    for (int o = 16; o; o >>= 1) sum += __shfl_xor_sync(~0u, sum, o);
    if ((t & 31) == 0) red[t >> 5] = sum;
    __syncthreads();
    sum = red[0] + red[1] + red[2] + red[3];
    float inv = PSCALE / sum;
    __half h, l;
    split_h(e0 * inv, h, l);
    Ph[row * ASTRIDE + j0] = h; Pl[row * ASTRIDE + j0] = l;
    if (j1 < ASTRIDE) {
        split_h(e1 * inv, h, l);
        Ph[row * ASTRIDE + j1] = h; Pl[row * ASTRIDE + j1] = l;
    }
}

// ---------------- V transpose: qkv halves -> Vt[bh][d][tok] (zero-padded) ------------
__global__ void vt_kernel(const __half* __restrict__ qkvh, const __half* __restrict__ qkvl,
                          __half* __restrict__ vth, __half* __restrict__ vtl, int N) {
    int bh = blockIdx.z;
    int b = bh / HEADS, hh = bh % HEADS;
    int t0 = blockIdx.x * 32, d0 = blockIdx.y * 32;
    __shared__ __half tile[2][32][33];
    int tx = threadIdx.x, ty = threadIdx.y;
#pragma unroll
    for (int i = 0; i < 4; i++) {
        int tok = t0 + ty + 8 * i, d = d0 + tx;
        __half vh = __float2half(0.f), vl = __float2half(0.f);
        if (tok < N) {
            size_t base = ((size_t)b * N + tok) * 1152 + 768 + hh * 64 + d;
            vh = qkvh[base]; vl = qkvl[base];
        }
        tile[0][ty + 8 * i][tx] = vh;
        tile[1][ty + 8 * i][tx] = vl;
    }
    __syncthreads();
#pragma unroll
    for (int i = 0; i < 4; i++) {
        int d = d0 + ty + 8 * i, tok = t0 + tx;
        size_t o = ((size_t)bh * 64 + d) * ASTRIDE + tok;
        vth[o] = tile[0][tx][ty + 8 * i];
        vtl[o] = tile[1][tx][ty + 8 * i];
    }
}

// ---------------- P @ V via fp16x2 mma -> split halves (x 1/256) ----------------
__global__ __launch_bounds__(128)
void av_fp16(const __half* __restrict__ Ph, const __half* __restrict__ Pl,
             const __half* __restrict__ Vth, const __half* __restrict__ Vtl,
             __half* __restrict__ aoh, __half* __restrict__ aol, int N) {
    int bh = blockIdx.y;
    int b = bh / HEADS, hh = bh % HEADS;
    int i0 = blockIdx.x * 64;
    __shared__ __align__(16) __half Ps[2][64][40];
    __shared__ __align__(16) __half Vs[2][64][40];
    int t = threadIdx.x, lane = t & 31, wid = t >> 5;
    int g = lane >> 2, q = lane & 3;
    int wm = wid >> 1, wn = wid & 1;
    const uint4 z4 = make_uint4(0, 0, 0, 0);

    float acc[2][4][4] = {};
    int nch = (N + 31) / 32;
    for (int c = 0; c < nch; c++) {
        int j0 = c * 32;
#pragma unroll
        for (int s = 0; s < 2; s++) {
            const __half* srcp = s ? Pl : Ph;
            const __half* srcv = s ? Vtl : Vth;
#pragma unroll
            for (int it = 0; it < 2; it++) {
                int idx = t + it * 128;
                int row = idx >> 2, cc = idx & 3;
                int gi = i0 + row;
                uint4 vp = z4;
                if (gi < N) vp = *(const uint4*)&srcp[((size_t)bh * N + gi) * ASTRIDE + j0 + 8 * cc];
                *(uint4*)&Ps[s][row][8 * cc] = vp;
                uint4 vv = *(const uint4*)&srcv[((size_t)bh * 64 + row) * ASTRIDE + j0 + 8 * cc];
                *(uint4*)&Vs[s][row][8 * cc] = vv;
            }
        }
        __syncthreads();
#pragma unroll
        for (int ks = 0; ks < 2; ks++) {
            int kb = ks * 16;
            unsigned aH[2][4], aL[2][4];
#pragma unroll
            for (int tm = 0; tm < 2; tm++) {
                int r0 = wm * 32 + tm * 16;
                aH[tm][0] = *(const unsigned*)&Ps[0][r0 + g][kb + 2 * q];
                aH[tm][1] = *(const unsigned*)&Ps[0][r0 + g + 8][kb + 2 * q];
                aH[tm][2] = *(const unsigned*)&Ps[0][r0 + g][kb + 2 * q + 8];
                aH[tm][3] = *(const unsigned*)&Ps[0][r0 + g + 8][kb + 2 * q + 8];
                aL[tm][0] = *(const unsigned*)&Ps[1][r0 + g][kb + 2 * q];
                aL[tm][1] = *(const unsigned*)&Ps[1][r0 + g + 8][kb + 2 * q];
                aL[tm][2] = *(const unsigned*)&Ps[1][r0 + g][kb + 2 * q + 8];
                aL[tm][3] = *(const unsigned*)&Ps[1][r0 + g + 8][kb + 2 * q + 8];
            }
            unsigned bH[4][2], bL[4][2];
#pragma unroll
            for (int tn = 0; tn < 4; tn++) {
                int n = wn * 32 + tn * 8 + g;
                bH[tn][0] = *(const unsigned*)&Vs[0][n][kb + 2 * q];
                bH[tn][1] = *(const unsigned*)&Vs[0][n][kb + 2 * q + 8];
                bL[tn][0] = *(const unsigned*)&Vs[1][n][kb + 2 * q];
                bL[tn][1] = *(const unsigned*)&Vs[1][n][kb + 2 * q + 8];
            }
#pragma unroll
            for (int tm = 0; tm < 2; tm++)
#pragma unroll
                for (int tn = 0; tn < 4; tn++) {
                    mma16(acc[tm][tn], aH[tm], bH[tn]);
                    mma16(acc[tm][tn], aH[tm], bL[tn]);
                    mma16(acc[tm][tn], aL[tm], bH[tn]);
                }
        }
        __syncthreads();
    }

#pragma unroll
    for (int tm = 0; tm < 2; tm++) {
#pragma unroll
        for (int tn = 0; tn < 4; tn++) {
            int d = wn * 32 + tn * 8 + 2 * q;
            int r0 = i0 + wm * 32 + tm * 16;
#pragma unroll
            for (int hf = 0; hf < 2; hf++) {
                int gi = r0 + g + 8 * hf;
                if (gi >= N) continue;
#pragma unroll
                for (int cc = 0; cc < 2; cc++) {
                    float v = acc[tm][tn][hf * 2 + cc] * INV_PSCALE;
                    size_t o = ((size_t)b * N + gi) * CDIM + hh * 64 + d + cc;
                    __half h, l;
                    split_h(v, h, l);
                    aoh[o] = h; aol[o] = l;
                }
            }
        }
    }
}

// ---------------- prune: head-mean CLS attention scores ----------------
__global__ void scoremean_kernel(const __half* __restrict__ Ph, const __half* __restrict__ Pl,
                                 float* __restrict__ scores, int N) {
    int Ntok = N - 1;
    int i = blockIdx.x * 256 + threadIdx.x;
    if (i >= BATCH * Ntok) return;
    int b = i / Ntok, j = i % Ntok;
    float s = 0.f;
#pragma unroll
    for (int hh = 0; hh < HEADS; hh++) {
        size_t o = ((size_t)(b * HEADS + hh) * N) * ASTRIDE + 1 + j;
        s += __half2float(Ph[o]) + __half2float(Pl[o]);
    }
    scores[i] = s;
}

__global__ __launch_bounds__(256)
void rank_kernel(const float* __restrict__ scores, int* __restrict__ idxout, int Ntok, int keep) {
    int b = blockIdx.x;
    __shared__ float s[256];
    int t = threadIdx.x;
    if (t < Ntok) s[t] = scores[b * Ntok + t];
    __syncthreads();
    if (t < Ntok) {
        float mine = s[t];
        int r = 0;
        for (int j = 0; j < Ntok; j++)
            r += (s[j] > mine) || (s[j] == mine && j < t);
        if (r < keep) idxout[b * keep + r] = t;
    }
}

__global__ void gather_kernel(const float* __restrict__ src, float* __restrict__ dst,
                              const int* __restrict__ idx, int N, int keep) {
    int newN = keep + 1;
    size_t TOT = (size_t)BATCH * newN * CDIM;
    size_t i = (size_t)blockIdx.x * 256 + threadIdx.x;
    if (i >= TOT) return;
    int c = i % CDIM;
    int r = (i / CDIM) % newN;
    int b = i / ((size_t)CDIM * newN);
    int sr = (r == 0) ? 0 : 1 + idx[b * keep + r - 1];
    dst[i] = src[((size_t)b * N + sr) * CDIM + c];
}

// ---------------- fused final LN (cls rows) + classification head ----------------
__global__ __launch_bounds__(128)
void head_kernel(const float* __restrict__ h, const float* __restrict__ g,
                 const float* __restrict__ bb, const float* __restrict__ W,
                 const float* __restrict__ wb, float* __restrict__ out, int N) {
    int b = blockIdx.x;
    const float* xr = h + (size_t)(b * N) * CDIM;
    __shared__ float sm[CDIM];
    int t = threadIdx.x;
    float v[3];
    float s = 0.f, s2 = 0.f;
#pragma unroll
    for (int l = 0; l < 3; l++) { v[l] = xr[t + 128 * l]; s += v[l]; s2 += v[l] * v[l]; }
#pragma unroll
    for (int o = 16; o; o >>= 1) {
        s  += __shfl_xor_sync(~0u, s, o);
        s2 += __shfl_xor_sync(~0u, s2, o);
    }
    __shared__ float ws[4], ws2[4];
    if ((t & 31) == 0) { ws[t >> 5] = s; ws2[t >> 5] = s2; }
    __syncthreads();
    s  = ws[0] + ws[1] + ws[2] + ws[3];
    s2 = ws2[0] + ws2[1] + ws2[2] + ws2[3];
    float mean = s * (1.f / CDIM);
    float var  = s2 * (1.f / CDIM) - mean * mean;
    float r = rsqrtf(var + EPSLN);
#pragma unroll
    for (int l = 0; l < 3; l++) {
        int c = t + 128 * l;
        sm[c] = (v[l] - mean) * r * g[c] + bb[c];
    }
    __syncthreads();
    if (t < NCLS) {
        float acc = wb[t];
        for (int k = 0; k < CDIM; k++)
            acc += sm[k] * W[k * NCLS + t];
        out[b * NCLS + t] = acc;
    }
}

// ---------------- launch ----------------
extern "C" void kernel_launch(void* const* d_in, const int* in_sizes, int n_in,
                              void* d_out, int out_size) {
    const float* x        = (const float*)d_in[0];
    const float* patch_w  = (const float*)d_in[1];
    const float* patch_b  = (const float*)d_in[2];
    const float* cls_tok  = (const float*)d_in[3];
    const float* pos_emb  = (const float*)d_in[4];
    const float* ln1_g    = (const float*)d_in[5];
    const float* ln1_b    = (const float*)d_in[6];
    const float* qkv_w    = (const float*)d_in[7];
    const float* qkv_b    = (const float*)d_in[8];
    const float* proj_w   = (const float*)d_in[9];
    const float* proj_b   = (const float*)d_in[10];
    const float* ln2_g    = (const float*)d_in[11];
    const float* ln2_b    = (const float*)d_in[12];
    const float* fc1_w    = (const float*)d_in[13];
    const float* fc1_b    = (const float*)d_in[14];
    const float* fc2_w    = (const float*)d_in[15];
    const float* fc2_b    = (const float*)d_in[16];
    const float* norm_g   = (const float*)d_in[17];
    const float* norm_b   = (const float*)d_in[18];
    const float* head_w   = (const float*)d_in[19];
    const float* head_b   = (const float*)d_in[20];

    float *h[2], *attnb, *pembed, *scoresb;
    int* idxb;
    __half *wth, *wtl, *lnh, *lnl, *qkvh, *qkvl, *vth, *vtl, *ph, *pl, *aoh, *aol, *mlph, *mlpl, *pxh, *pxl;
    cudaGetSymbolAddress((void**)&h[0], g_h0);
    cudaGetSymbolAddress((void**)&h[1], g_h1);
    cudaGetSymbolAddress((void**)&attnb, g_attn);
    cudaGetSymbolAddress((void**)&pembed, g_pembed);
    cudaGetSymbolAddress((void**)&scoresb, g_scores);
    cudaGetSymbolAddress((void**)&idxb, g_idx);
    cudaGetSymbolAddress((void**)&wth, g_wth);
    cudaGetSymbolAddress((void**)&wtl, g_wtl);
    cudaGetSymbolAddress((void**)&lnh, g_lnh);
    cudaGetSymbolAddress((void**)&lnl, g_lnl);
    cudaGetSymbolAddress((void**)&qkvh, g_qkvh);
    cudaGetSymbolAddress((void**)&qkvl, g_qkvl);
    cudaGetSymbolAddress((void**)&vth, g_vth);
    cudaGetSymbolAddress((void**)&vtl, g_vtl);
    cudaGetSymbolAddress((void**)&ph, g_ph);
    cudaGetSymbolAddress((void**)&pl, g_pl);
    cudaGetSymbolAddress((void**)&aoh, g_aoh);
    cudaGetSymbolAddress((void**)&aol, g_aol);
    cudaGetSymbolAddress((void**)&mlph, g_mlph);
    cudaGetSymbolAddress((void**)&mlpl, g_mlpl);
    cudaGetSymbolAddress((void**)&pxh, g_pxh);
    cudaGetSymbolAddress((void**)&pxl, g_pxl);

    // ---- weight transpose + split (once per call) ----
    {
        dim3 blk(32, 8);
        wsplit_kernel<<<dim3(768 / 32, 384 / 32, 1), blk>>>(patch_w, 0, wth + OFF_PATCH, wtl + OFF_PATCH, 0, 768, 384);
        wsplit_kernel<<<dim3(384 / 32, 1152 / 32, 12), blk>>>(qkv_w, (size_t)384 * 1152, wth + OFF_QKV, wtl + OFF_QKV, SZ_QKV, 384, 1152);
        wsplit_kernel<<<dim3(384 / 32, 384 / 32, 12), blk>>>(proj_w, (size_t)384 * 384, wth + OFF_PROJ, wtl + OFF_PROJ, SZ_PROJ, 384, 384);
        wsplit_kernel<<<dim3(384 / 32, 1536 / 32, 12), blk>>>(fc1_w, (size_t)384 * 1536, wth + OFF_FC1, wtl + OFF_FC1, SZ_FC1, 384, 1536);
        wsplit_kernel<<<dim3(1536 / 32, 384 / 32, 12), blk>>>(fc2_w, (size_t)1536 * 384, wth + OFF_FC2, wtl + OFF_FC2, SZ_FC2, 1536, 384);
    }

    // ---- patch embed ----
    {
        int tot = BATCH * NPATCH * 768;
        patchify_kernel<<<(tot + 255) / 256, 256>>>(x, pxh, pxl);
        int M = BATCH * NPATCH;
        gemm_fp16<0, true, false><<<dim3(CDIM / 64, (M + 127) / 128), 256>>>(
            pxh, pxl, wth + OFF_PATCH, wtl + OFF_PATCH, patch_b, nullptr,
            pembed, nullptr, nullptr, M, 768, CDIM, INV_WSCALE);
        int tot2 = BATCH * MAXN * CDIM;
        assemble_kernel<<<(tot2 + 255) / 256, 256>>>(pembed, cls_tok, pos_emb, h[0]);
    }

    int cur = 0;
    int N = MAXN;
    for (int l = 0; l < LAYERS; l++) {
        int M = BATCH * N;
        // attention
        ln_kernel<<<M, 128>>>(h[cur], ln1_g + l * CDIM, ln1_b + l * CDIM, lnh, lnl);
        gemm_fp16<0, false, true><<<dim3(1152 / 64, (M + 127) / 128), 256>>>(
            lnh, lnl, wth + OFF_QKV + (size_t)l * SZ_QKV, wtl + OFF_QKV + (size_t)l * SZ_QKV,
            qkv_b + l * 1152, nullptr, nullptr, qkvh, qkvl, M, CDIM, 1152, INV_WSCALE);
        vt_kernel<<<dim3(ASTRIDE / 32, 2, BATCH * HEADS), dim3(32, 8)>>>(qkvh, qkvl, vth, vtl, N);
        int nt = (N + 63) / 64;
        qk_fp16<<<dim3(nt, nt, BATCH * HEADS), 128>>>(qkvh, qkvl, attnb, N);
        softmax_fp16<<<BATCH * HEADS * N, 128>>>(attnb, ph, pl, N);
        av_fp16<<<dim3(nt, BATCH * HEADS), 128>>>(ph, pl, vth, vtl, aoh, aol, N);
        gemm_fp16<1, true, false><<<dim3(CDIM / 64, (M + 127) / 128), 256>>>(
            aoh, aol, wth + OFF_PROJ + (size_t)l * SZ_PROJ, wtl + OFF_PROJ + (size_t)l * SZ_PROJ,
            proj_b + l * CDIM, h[cur], h[cur], nullptr, nullptr, M, CDIM, CDIM, INV_WSCALE);
        // prune
        if (l == 2 || l == 4 || l == 6) {
            int keep = (l == 2) ? 176 : (l == 4) ? 149 : 119;
            int Ntok = N - 1;
            scoremean_kernel<<<(BATCH * Ntok + 255) / 256, 256>>>(ph, pl, scoresb, N);
            rank_kernel<<<BATCH, 256>>>(scoresb, idxb, Ntok, keep);
            int newN = keep + 1;
            size_t tot = (size_t)BATCH * newN * CDIM;
            gather_kernel<<<(int)((tot + 255) / 256), 256>>>(h[cur], h[1 - cur], idxb, N, keep);
            cur ^= 1;
            N = newN;
            M = BATCH * N;
        }
        // mlp
        ln_kernel<<<M, 128>>>(h[cur], ln2_g + l * CDIM, ln2_b + l * CDIM, lnh, lnl);
        gemm_fp16<2, false, true><<<dim3(MLPD / 64, (M + 127) / 128), 256>>>(
            lnh, lnl, wth + OFF_FC1 + (size_t)l * SZ_FC1, wtl + OFF_FC1 + (size_t)l * SZ_FC1,
            fc1_b + l * MLPD, nullptr, nullptr, mlph, mlpl, M, CDIM, MLPD, INV_WSCALE);
        gemm_fp16<1, true, false><<<dim3(CDIM / 64, (M + 127) / 128), 256>>>(
            mlph, mlpl, wth + OFF_FC2 + (size_t)l * SZ_FC2, wtl + OFF_FC2 + (size_t)l * SZ_FC2,
            fc2_b + l * CDIM, h[cur], h[cur], nullptr, nullptr, M, MLPD, CDIM, INV_WSCALE);
    }

    head_kernel<<<BATCH, 128>>>(h[cur], norm_g, norm_b, head_w, head_b, (float*)d_out, N);
}

// round 7
// speedup vs baseline: 2.1154x; 1.0250x over previous
#include <cuda_runtime.h>
#include <cuda_fp16.h>
#include <stdint.h>
#include <stddef.h>
#include <math.h>

// ---------------- problem constants ----------------
#define BATCH   64
#define CDIM    384
#define HEADS   6
#define MLPD    1536
#define LAYERS  12
#define NPATCH  196
#define MAXN    197
#define NCLS    100
#define EPSLN   1e-6f
#define SCALE   0.125f
#define ASTRIDE 224
#define WSCALE     64.f
#define INV_WSCALE (1.f/64.f)
#define PSCALE     256.f
#define INV_PSCALE (1.f/256.f)

// transposed-weight half array offsets
#define SZ_PATCH (768*384)
#define SZ_QKV   (384*1152)
#define SZ_PROJ  (384*384)
#define SZ_FC1   (384*1536)
#define SZ_FC2   (1536*384)
#define OFF_PATCH 0
#define OFF_QKV   (SZ_PATCH)
#define OFF_PROJ  (OFF_QKV + 12*SZ_QKV)
#define OFF_FC1   (OFF_PROJ + 12*SZ_PROJ)
#define OFF_FC2   (OFF_FC1 + 12*SZ_FC1)
#define WTOTAL    (OFF_FC2 + 12*SZ_FC2)

// ---------------- device scratch ----------------
__device__ float  g_h0[(size_t)BATCH * MAXN * CDIM];
__device__ float  g_h1[(size_t)BATCH * MAXN * CDIM];
__device__ float  g_pembed[(size_t)BATCH * NPATCH * CDIM];
__device__ float  g_scores[BATCH * NPATCH];
__device__ int    g_idx[BATCH * NPATCH];

__device__ __half g_wth[(size_t)WTOTAL];
__device__ __half g_wtl[(size_t)WTOTAL];
__device__ __half g_lnh[(size_t)BATCH * MAXN * CDIM];
__device__ __half g_lnl[(size_t)BATCH * MAXN * CDIM];
__device__ __half g_qkvh[(size_t)BATCH * MAXN * 1152];
__device__ __half g_qkvl[(size_t)BATCH * MAXN * 1152];
__device__ __half g_vth[(size_t)BATCH * HEADS * 64 * ASTRIDE];
__device__ __half g_vtl[(size_t)BATCH * HEADS * 64 * ASTRIDE];
__device__ __half g_ph[(size_t)BATCH * HEADS * MAXN * ASTRIDE];
__device__ __half g_pl[(size_t)BATCH * HEADS * MAXN * ASTRIDE];
__device__ __half g_aoh[(size_t)BATCH * MAXN * CDIM];
__device__ __half g_aol[(size_t)BATCH * MAXN * CDIM];
__device__ __half g_mlph[(size_t)BATCH * MAXN * MLPD];
__device__ __half g_mlpl[(size_t)BATCH * MAXN * MLPD];
__device__ __half g_pxh[(size_t)BATCH * NPATCH * 768];
__device__ __half g_pxl[(size_t)BATCH * NPATCH * 768];

// ---------------- helpers ----------------
__device__ __forceinline__ void split_h(float v, __half& h, __half& l) {
    h = __float2half_rn(v);
    l = __float2half_rn(v - __half2float(h));
}

__device__ __forceinline__ void mma16(float* c, const unsigned* a, const unsigned* b) {
    asm volatile(
        "mma.sync.aligned.m16n8k16.row.col.f32.f16.f16.f32 "
        "{%0,%1,%2,%3},{%4,%5,%6,%7},{%8,%9},{%0,%1,%2,%3};"
        : "+f"(c[0]), "+f"(c[1]), "+f"(c[2]), "+f"(c[3])
        : "r"(a[0]), "r"(a[1]), "r"(a[2]), "r"(a[3]), "r"(b[0]), "r"(b[1]));
}

__device__ __forceinline__ unsigned cvta_s(const void* p) {
    unsigned a;
    asm("{ .reg .u64 t; cvta.to.shared.u64 t, %1; cvt.u32.u64 %0, t; }" : "=r"(a) : "l"(p));
    return a;
}

__device__ __forceinline__ void cp16(unsigned dst, const void* src, unsigned sz) {
    asm volatile("cp.async.cg.shared.global [%0], [%1], 16, %2;"
                 :: "r"(dst), "l"(src), "r"(sz) : "memory");
}
#define CP_COMMIT() asm volatile("cp.async.commit_group;" ::: "memory")
#define CP_WAIT1()  asm volatile("cp.async.wait_group 1;" ::: "memory")
#define CP_WAIT0()  asm volatile("cp.async.wait_group 0;" ::: "memory")

// ---------------- fp16x3 GEMM with cp.async double buffering ----------------
// tile 128x64, 256 thr (8 warps 4x2), warp 32x32, k-chunk 32.
// dyn smem (halves): A[buf][split][128][40] then B[buf][split][64][40]
// EPI: 0 bias, 1 bias+res, 2 bias+gelu
#define GEMM_SMEM 61440

__device__ __forceinline__ void gemm_issue(
    unsigned sb, const __half* Ah, const __half* Al,
    const __half* Bth, const __half* Btl,
    int M, int K, int m0, int n0, int t, int c) {
    int p = c & 1;
    int kb = c * 32;
#pragma unroll
    for (int s = 0; s < 2; s++) {
        const __half* asrc = s ? Al : Ah;
#pragma unroll
        for (int it = 0; it < 2; it++) {
            int idx = t + it * 256;
            int row = idx >> 2, c4 = idx & 3;
            int gm = m0 + row;
            int gmc = (gm < M) ? gm : (M - 1);
            const __half* src = asrc + (size_t)gmc * K + kb + 8 * c4;
            unsigned dst = sb + (unsigned)(p * 10240 + s * 5120 + row * 40 + 8 * c4) * 2u;
            cp16(dst, src, (gm < M) ? 16u : 0u);
        }
        const __half* bsrc = s ? Btl : Bth;
        int brow = t >> 2, bc4 = t & 3;
        const __half* srcb = bsrc + (size_t)(n0 + brow) * K + kb + 8 * bc4;
        unsigned dstb = sb + (unsigned)(20480 + p * 5120 + s * 2560 + brow * 40 + 8 * bc4) * 2u;
        cp16(dstb, srcb, 16u);
    }
    CP_COMMIT();
}

template<int EPI, bool OF32, bool OHALF>
__global__ __launch_bounds__(256, 2)
void gemm_fp16(const __half* __restrict__ Ah, const __half* __restrict__ Al,
               const __half* __restrict__ Bth, const __half* __restrict__ Btl,
               const float* __restrict__ bias, const float* __restrict__ res,
               float* __restrict__ C32, __half* __restrict__ Ch, __half* __restrict__ Cl,
               int M, int K, int Nout, float oscale) {
    extern __shared__ __half smp[];
    unsigned sb = cvta_s(smp);
    int t = threadIdx.x, lane = t & 31, wid = t >> 5;
    int g = lane >> 2, q = lane & 3;
    int wm = wid >> 1, wn = wid & 1;
    int m0 = blockIdx.y * 128, n0 = blockIdx.x * 64;
    float acc[2][4][4] = {};
    int nch = K >> 5;

    gemm_issue(sb, Ah, Al, Bth, Btl, M, K, m0, n0, t, 0);
    for (int c = 0; c < nch; c++) {
        if (c + 1 < nch) {
            gemm_issue(sb, Ah, Al, Bth, Btl, M, K, m0, n0, t, c + 1);
            CP_WAIT1();
        } else {
            CP_WAIT0();
        }
        __syncthreads();
        int p = c & 1;
        const __half* Ab = smp + p * 10240;
        const __half* Bb = smp + 20480 + p * 5120;
#pragma unroll
        for (int ks = 0; ks < 2; ks++) {
            int kb = ks * 16;
            unsigned aH[2][4], aL[2][4];
#pragma unroll
            for (int tm = 0; tm < 2; tm++) {
                int r0 = wm * 32 + tm * 16;
                const __half* a0 = Ab + (r0 + g) * 40;
                const __half* a8 = Ab + (r0 + g + 8) * 40;
                aH[tm][0] = *(const unsigned*)(a0 + kb + 2 * q);
                aH[tm][1] = *(const unsigned*)(a8 + kb + 2 * q);
                aH[tm][2] = *(const unsigned*)(a0 + kb + 2 * q + 8);
                aH[tm][3] = *(const unsigned*)(a8 + kb + 2 * q + 8);
                const __half* l0 = a0 + 5120;
                const __half* l8 = a8 + 5120;
                aL[tm][0] = *(const unsigned*)(l0 + kb + 2 * q);
                aL[tm][1] = *(const unsigned*)(l8 + kb + 2 * q);
                aL[tm][2] = *(const unsigned*)(l0 + kb + 2 * q + 8);
                aL[tm][3] = *(const unsigned*)(l8 + kb + 2 * q + 8);
            }
            unsigned bH[4][2], bL[4][2];
#pragma unroll
            for (int tn = 0; tn < 4; tn++) {
                int n = wn * 32 + tn * 8 + g;
                const __half* b0 = Bb + n * 40;
                bH[tn][0] = *(const unsigned*)(b0 + kb + 2 * q);
                bH[tn][1] = *(const unsigned*)(b0 + kb + 2 * q + 8);
                const __half* bl = b0 + 2560;
                bL[tn][0] = *(const unsigned*)(bl + kb + 2 * q);
                bL[tn][1] = *(const unsigned*)(bl + kb + 2 * q + 8);
            }
#pragma unroll
            for (int tm = 0; tm < 2; tm++)
#pragma unroll
                for (int tn = 0; tn < 4; tn++) {
                    mma16(acc[tm][tn], aH[tm], bH[tn]);
                    mma16(acc[tm][tn], aH[tm], bL[tn]);
                    mma16(acc[tm][tn], aL[tm], bH[tn]);
                }
        }
        __syncthreads();
    }

#pragma unroll
    for (int tm = 0; tm < 2; tm++) {
#pragma unroll
        for (int tn = 0; tn < 4; tn++) {
            int col = n0 + wn * 32 + tn * 8 + 2 * q;
            int r0 = m0 + wm * 32 + tm * 16;
#pragma unroll
            for (int hf = 0; hf < 2; hf++) {
                int gm = r0 + g + 8 * hf;
                if (gm >= M) continue;
#pragma unroll
                for (int cc = 0; cc < 2; cc++) {
                    float v = acc[tm][tn][hf * 2 + cc] * oscale + bias[col + cc];
                    if (EPI == 1) v += res[(size_t)gm * Nout + col + cc];
                    if (EPI == 2) v = 0.5f * v * (1.f + erff(v * 0.70710678118654752f));
                    if (OF32) C32[(size_t)gm * Nout + col + cc] = v;
                    if (OHALF) {
                        __half hh, ll;
                        split_h(v, hh, ll);
                        Ch[(size_t)gm * Nout + col + cc] = hh;
                        Cl[(size_t)gm * Nout + col + cc] = ll;
                    }
                }
            }
        }
    }
}

// ---------------- weight transpose + split:  Wt[n][k] = W[k][n] * 64 ----------------
__global__ void wsplit_kernel(const float* __restrict__ W, size_t in_lstride,
                              __half* __restrict__ oh, __half* __restrict__ ol,
                              size_t out_lstride, int K, int N) {
    __shared__ float tile[32][33];
    int k0 = blockIdx.x * 32, n0 = blockIdx.y * 32;
    const float* Wl = W + (size_t)blockIdx.z * in_lstride;
    __half* ohl = oh + (size_t)blockIdx.z * out_lstride;
    __half* oll = ol + (size_t)blockIdx.z * out_lstride;
    int tx = threadIdx.x, ty = threadIdx.y;
#pragma unroll
    for (int i = 0; i < 4; i++)
        tile[ty + 8 * i][tx] = Wl[(size_t)(k0 + ty + 8 * i) * N + n0 + tx];
    __syncthreads();
#pragma unroll
    for (int i = 0; i < 4; i++) {
        int n = n0 + ty + 8 * i, k = k0 + tx;
        float v = tile[tx][ty + 8 * i] * WSCALE;
        __half h, l;
        split_h(v, h, l);
        ohl[(size_t)n * K + k] = h;
        oll[(size_t)n * K + k] = l;
    }
}

// ---------------- patchify + split ----------------
__global__ void patchify_kernel(const float* __restrict__ x,
                                __half* __restrict__ ph, __half* __restrict__ pl) {
    int i = blockIdx.x * 256 + threadIdx.x;
    const int TOT = BATCH * NPATCH * 768;
    if (i >= TOT) return;
    int k  = i % 768;
    int tt = (i / 768) % NPATCH;
    int b  = i / (768 * NPATCH);
    int ch = k >> 8, py = (k >> 4) & 15, px = k & 15;
    int gy = tt / 14, gx = tt % 14;
    float v = x[(((size_t)b * 3 + ch) * 224 + gy * 16 + py) * 224 + gx * 16 + px];
    split_h(v, ph[i], pl[i]);
}

// ---------------- assemble: cls + patch-embed + pos ----------------
__global__ void assemble_kernel(const float* __restrict__ pe, const float* __restrict__ cls,
                                const float* __restrict__ pos, float* __restrict__ h) {
    int i = blockIdx.x * 256 + threadIdx.x;
    const int TOT = BATCH * MAXN * CDIM;
    if (i >= TOT) return;
    int c = i % CDIM;
    int r = (i / CDIM) % MAXN;
    int b = i / (CDIM * MAXN);
    float v = (r == 0) ? cls[c] : pe[((size_t)b * NPATCH + (r - 1)) * CDIM + c];
    h[i] = v + pos[r * CDIM + c];
}

// ---------------- LayerNorm -> split halves ----------------
__global__ __launch_bounds__(128)
void ln_kernel(const float* __restrict__ x, const float* __restrict__ g,
               const float* __restrict__ bb, __half* __restrict__ yh, __half* __restrict__ yl) {
    size_t row = blockIdx.x;
    const float* xr = x + row * CDIM;
    int t = threadIdx.x;
    float v[3];
    float s = 0.f, s2 = 0.f;
#pragma unroll
    for (int l = 0; l < 3; l++) { v[l] = xr[t + 128 * l]; s += v[l]; s2 += v[l] * v[l]; }
#pragma unroll
    for (int o = 16; o; o >>= 1) {
        s  += __shfl_xor_sync(~0u, s, o);
        s2 += __shfl_xor_sync(~0u, s2, o);
    }
    __shared__ float ws[4], ws2[4];
    if ((t & 31) == 0) { ws[t >> 5] = s; ws2[t >> 5] = s2; }
    __syncthreads();
    s  = ws[0] + ws[1] + ws[2] + ws[3];
    s2 = ws2[0] + ws2[1] + ws2[2] + ws2[3];
    float mean = s * (1.f / CDIM);
    float var  = s2 * (1.f / CDIM) - mean * mean;
    float r = rsqrtf(var + EPSLN);
#pragma unroll
    for (int l = 0; l < 3; l++) {
        int c = t + 128 * l;
        float o = (v[l] - mean) * r * g[c] + bb[c];
        split_h(o, yh[row * CDIM + c], yl[row * CDIM + c]);
    }
}

// ---------------- fused QK^T + softmax -> split Ph/Pl (x256) -------------------------
// grid (ceil(N/64), B*H), 128 thr. Q tile resident; loops K tiles; logits in smem.
#define QKS_SMEM 95488
__global__ __launch_bounds__(128)
void qk_softmax(const __half* __restrict__ qh, const __half* __restrict__ ql,
                __half* __restrict__ Ph, __half* __restrict__ Pl, int N) {
    extern __shared__ char qsm[];
    __half* Qs = (__half*)qsm;                   // [2][64][72]
    __half* Ks = (__half*)(qsm + 18432);         // [2][64][72]
    float* logits = (float*)(qsm + 36864);       // [64][228]
    float* rowinv = (float*)(qsm + 36864 + 58368);
    int bh = blockIdx.y;
    int b = bh / HEADS, hh = bh % HEADS;
    int i0 = blockIdx.x * 64;
    int t = threadIdx.x, lane = t & 31, wid = t >> 5;
    int g = lane >> 2, q = lane & 3;
    int wm = wid >> 1, wn = wid & 1;
    const uint4 z4 = make_uint4(0, 0, 0, 0);

    // load Q tile once
#pragma unroll
    for (int s = 0; s < 2; s++) {
        const __half* src = s ? ql : qh;
#pragma unroll
        for (int it = 0; it < 4; it++) {
            int idx = t + it * 128;
            int row = idx >> 3, c = idx & 7;
            int gi = i0 + row;
            uint4 v = z4;
            if (gi < N) v = *(const uint4*)&src[((size_t)b * N + gi) * 1152 + hh * 64 + 8 * c];
            *(uint4*)&Qs[s * 4608 + row * 72 + 8 * c] = v;
        }
    }

    int ntj = (N + 63) / 64;
    for (int jt = 0; jt < ntj; jt++) {
        int j0 = jt * 64;
        // load K tile
#pragma unroll
        for (int s = 0; s < 2; s++) {
            const __half* src = s ? ql : qh;
#pragma unroll
            for (int it = 0; it < 4; it++) {
                int idx = t + it * 128;
                int row = idx >> 3, c = idx & 7;
                int gj = j0 + row;
                uint4 v = z4;
                if (gj < N) v = *(const uint4*)&src[((size_t)b * N + gj) * 1152 + 384 + hh * 64 + 8 * c];
                *(uint4*)&Ks[s * 4608 + row * 72 + 8 * c] = v;
            }
        }
        __syncthreads();

        float acc[2][4][4] = {};
#pragma unroll
        for (int ks = 0; ks < 4; ks++) {
            int kb = ks * 16;
            unsigned aH[2][4], aL[2][4];
#pragma unroll
            for (int tm = 0; tm < 2; tm++) {
                int r0 = wm * 32 + tm * 16;
                const __half* a0 = Qs + (r0 + g) * 72;
                const __half* a8 = Qs + (r0 + g + 8) * 72;
                aH[tm][0] = *(const unsigned*)(a0 + kb + 2 * q);
                aH[tm][1] = *(const unsigned*)(a8 + kb + 2 * q);
                aH[tm][2] = *(const unsigned*)(a0 + kb + 2 * q + 8);
                aH[tm][3] = *(const unsigned*)(a8 + kb + 2 * q + 8);
                aL[tm][0] = *(const unsigned*)(a0 + 4608 + kb + 2 * q);
                aL[tm][1] = *(const unsigned*)(a8 + 4608 + kb + 2 * q);
                aL[tm][2] = *(const unsigned*)(a0 + 4608 + kb + 2 * q + 8);
                aL[tm][3] = *(const unsigned*)(a8 + 4608 + kb + 2 * q + 8);
            }
            unsigned bH[4][2], bL[4][2];
#pragma unroll
            for (int tn = 0; tn < 4; tn++) {
                int n = wn * 32 + tn * 8 + g;
                const __half* b0 = Ks + n * 72;
                bH[tn][0] = *(const unsigned*)(b0 + kb + 2 * q);
                bH[tn][1] = *(const unsigned*)(b0 + kb + 2 * q + 8);
                bL[tn][0] = *(const unsigned*)(b0 + 4608 + kb + 2 * q);
                bL[tn][1] = *(const unsigned*)(b0 + 4608 + kb + 2 * q + 8);
            }
#pragma unroll
            for (int tm = 0; tm < 2; tm++)
#pragma unroll
                for (int tn = 0; tn < 4; tn++) {
                    mma16(acc[tm][tn], aH[tm], bH[tn]);
                    mma16(acc[tm][tn], aH[tm], bL[tn]);
                    mma16(acc[tm][tn], aL[tm], bH[tn]);
                }
        }

        // write logits to smem
#pragma unroll
        for (int tm = 0; tm < 2; tm++) {
#pragma unroll
            for (int tn = 0; tn < 4; tn++) {
                int col = j0 + wn * 32 + tn * 8 + 2 * q;
                int r0l = wm * 32 + tm * 16;
#pragma unroll
                for (int hf = 0; hf < 2; hf++) {
                    int li = r0l + g + 8 * hf;
                    if (i0 + li >= N) continue;
#pragma unroll
                    for (int cc = 0; cc < 2; cc++) {
                        int gj = col + cc;
                        if (gj < N) logits[li * 228 + gj] = acc[tm][tn][hf * 2 + cc] * SCALE;
                    }
                }
            }
        }
        __syncthreads();
    }

    // softmax: 2 threads per row
    {
        int rr = t >> 1, part = t & 1;
        int c0 = part * 112;
        float mx = -1e30f;
        for (int c = c0; c < c0 + 112; c++)
            if (c < N) mx = fmaxf(mx, logits[rr * 228 + c]);
        mx = fmaxf(mx, __shfl_xor_sync(~0u, mx, 1));
        float sum = 0.f;
        for (int c = c0; c < c0 + 112; c++) {
            float e = (c < N) ? expf(logits[rr * 228 + c] - mx) : 0.f;
            logits[rr * 228 + c] = e;
            sum += e;
        }
        sum += __shfl_xor_sync(~0u, sum, 1);
        if (part == 0) rowinv[rr] = PSCALE / fmaxf(sum, 1e-30f);
    }
    __syncthreads();

    // coalesced write of split probabilities (zero-padded to ASTRIDE)
    for (int i = t; i < 64 * ASTRIDE; i += 128) {
        int r2 = i / ASTRIDE, c2 = i % ASTRIDE;
        int gi2 = i0 + r2;
        if (gi2 >= N) continue;
        float v = (c2 < N) ? logits[r2 * 228 + c2] * rowinv[r2] : 0.f;
        __half hh2, ll2;
        split_h(v, hh2, ll2);
        size_t o = ((size_t)bh * N + gi2) * ASTRIDE + c2;
        Ph[o] = hh2;
        Pl[o] = ll2;
    }
}

// ---------------- V transpose: qkv halves -> Vt[bh][d][tok] (zero-padded) ------------
__global__ void vt_kernel(const __half* __restrict__ qkvh, const __half* __restrict__ qkvl,
                          __half* __restrict__ vth, __half* __restrict__ vtl, int N) {
    int bh = blockIdx.z;
    int b = bh / HEADS, hh = bh % HEADS;
    int t0 = blockIdx.x * 32, d0 = blockIdx.y * 32;
    __shared__ __half tile[2][32][33];
    int tx = threadIdx.x, ty = threadIdx.y;
#pragma unroll
    for (int i = 0; i < 4; i++) {
        int tok = t0 + ty + 8 * i, d = d0 + tx;
        __half vh = __float2half(0.f), vl = __float2half(0.f);
        if (tok < N) {
            size_t base = ((size_t)b * N + tok) * 1152 + 768 + hh * 64 + d;
            vh = qkvh[base]; vl = qkvl[base];
        }
        tile[0][ty + 8 * i][tx] = vh;
        tile[1][ty + 8 * i][tx] = vl;
    }
    __syncthreads();
#pragma unroll
    for (int i = 0; i < 4; i++) {
        int d = d0 + ty + 8 * i, tok = t0 + tx;
        size_t o = ((size_t)bh * 64 + d) * ASTRIDE + tok;
        vth[o] = tile[0][tx][ty + 8 * i];
        vtl[o] = tile[1][tx][ty + 8 * i];
    }
}

// ---------------- P @ V via fp16x2 mma -> split halves (x 1/256) ----------------
__global__ __launch_bounds__(128)
void av_fp16(const __half* __restrict__ Ph, const __half* __restrict__ Pl,
             const __half* __restrict__ Vth, const __half* __restrict__ Vtl,
             __half* __restrict__ aoh, __half* __restrict__ aol, int N) {
    int bh = blockIdx.y;
    int b = bh / HEADS, hh = bh % HEADS;
    int i0 = blockIdx.x * 64;
    __shared__ __align__(16) __half Ps[2][64][40];
    __shared__ __align__(16) __half Vs[2][64][40];
    int t = threadIdx.x, lane = t & 31, wid = t >> 5;
    int g = lane >> 2, q = lane & 3;
    int wm = wid >> 1, wn = wid & 1;
    const uint4 z4 = make_uint4(0, 0, 0, 0);

    float acc[2][4][4] = {};
    int nch = (N + 31) / 32;
    for (int c = 0; c < nch; c++) {
        int j0 = c * 32;
#pragma unroll
        for (int s = 0; s < 2; s++) {
            const __half* srcp = s ? Pl : Ph;
            const __half* srcv = s ? Vtl : Vth;
#pragma unroll
            for (int it = 0; it < 2; it++) {
                int idx = t + it * 128;
                int row = idx >> 2, cc = idx & 3;
                int gi = i0 + row;
                uint4 vp = z4;
                if (gi < N) vp = *(const uint4*)&srcp[((size_t)bh * N + gi) * ASTRIDE + j0 + 8 * cc];
                *(uint4*)&Ps[s][row][8 * cc] = vp;
                uint4 vv = *(const uint4*)&srcv[((size_t)bh * 64 + row) * ASTRIDE + j0 + 8 * cc];
                *(uint4*)&Vs[s][row][8 * cc] = vv;
            }
        }
        __syncthreads();
#pragma unroll
        for (int ks = 0; ks < 2; ks++) {
            int kb = ks * 16;
            unsigned aH[2][4], aL[2][4];
#pragma unroll
            for (int tm = 0; tm < 2; tm++) {
                int r0 = wm * 32 + tm * 16;
                aH[tm][0] = *(const unsigned*)&Ps[0][r0 + g][kb + 2 * q];
                aH[tm][1] = *(const unsigned*)&Ps[0][r0 + g + 8][kb + 2 * q];
                aH[tm][2] = *(const unsigned*)&Ps[0][r0 + g][kb + 2 * q + 8];
                aH[tm][3] = *(const unsigned*)&Ps[0][r0 + g + 8][kb + 2 * q + 8];
                aL[tm][0] = *(const unsigned*)&Ps[1][r0 + g][kb + 2 * q];
                aL[tm][1] = *(const unsigned*)&Ps[1][r0 + g + 8][kb + 2 * q];
                aL[tm][2] = *(const unsigned*)&Ps[1][r0 + g][kb + 2 * q + 8];
                aL[tm][3] = *(const unsigned*)&Ps[1][r0 + g + 8][kb + 2 * q + 8];
            }
            unsigned bH[4][2], bL[4][2];
#pragma unroll
            for (int tn = 0; tn < 4; tn++) {
                int n = wn * 32 + tn * 8 + g;
                bH[tn][0] = *(const unsigned*)&Vs[0][n][kb + 2 * q];
                bH[tn][1] = *(const unsigned*)&Vs[0][n][kb + 2 * q + 8];
                bL[tn][0] = *(const unsigned*)&Vs[1][n][kb + 2 * q];
                bL[tn][1] = *(const unsigned*)&Vs[1][n][kb + 2 * q + 8];
            }
#pragma unroll
            for (int tm = 0; tm < 2; tm++)
#pragma unroll
                for (int tn = 0; tn < 4; tn++) {
                    mma16(acc[tm][tn], aH[tm], bH[tn]);
                    mma16(acc[tm][tn], aH[tm], bL[tn]);
                    mma16(acc[tm][tn], aL[tm], bH[tn]);
                }
        }
        __syncthreads();
    }

#pragma unroll
    for (int tm = 0; tm < 2; tm++) {
#pragma unroll
        for (int tn = 0; tn < 4; tn++) {
            int d = wn * 32 + tn * 8 + 2 * q;
            int r0 = i0 + wm * 32 + tm * 16;
#pragma unroll
            for (int hf = 0; hf < 2; hf++) {
                int gi = r0 + g + 8 * hf;
                if (gi >= N) continue;
#pragma unroll
                for (int cc = 0; cc < 2; cc++) {
                    float v = acc[tm][tn][hf * 2 + cc] * INV_PSCALE;
                    size_t o = ((size_t)b * N + gi) * CDIM + hh * 64 + d + cc;
                    __half h, l;
                    split_h(v, h, l);
                    aoh[o] = h; aol[o] = l;
                }
            }
        }
    }
}

// ---------------- prune: head-mean CLS attention scores ----------------
__global__ void scoremean_kernel(const __half* __restrict__ Ph, const __half* __restrict__ Pl,
                                 float* __restrict__ scores, int N) {
    int Ntok = N - 1;
    int i = blockIdx.x * 256 + threadIdx.x;
    if (i >= BATCH * Ntok) return;
    int b = i / Ntok, j = i % Ntok;
    float s = 0.f;
#pragma unroll
    for (int hh = 0; hh < HEADS; hh++) {
        size_t o = ((size_t)(b * HEADS + hh) * N) * ASTRIDE + 1 + j;
        s += __half2float(Ph[o]) + __half2float(Pl[o]);
    }
    scores[i] = s;
}

__global__ __launch_bounds__(256)
void rank_kernel(const float* __restrict__ scores, int* __restrict__ idxout, int Ntok, int keep) {
    int b = blockIdx.x;
    __shared__ float s[256];
    int t = threadIdx.x;
    if (t < Ntok) s[t] = scores[b * Ntok + t];
    __syncthreads();
    if (t < Ntok) {
        float mine = s[t];
        int r = 0;
        for (int j = 0; j < Ntok; j++)
            r += (s[j] > mine) || (s[j] == mine && j < t);
        if (r < keep) idxout[b * keep + r] = t;
    }
}

__global__ void gather_kernel(const float* __restrict__ src, float* __restrict__ dst,
                              const int* __restrict__ idx, int N, int keep) {
    int newN = keep + 1;
    size_t TOT = (size_t)BATCH * newN * CDIM;
    size_t i = (size_t)blockIdx.x * 256 + threadIdx.x;
    if (i >= TOT) return;
    int c = i % CDIM;
    int r = (i / CDIM) % newN;
    int b = i / ((size_t)CDIM * newN);
    int sr = (r == 0) ? 0 : 1 + idx[b * keep + r - 1];
    dst[i] = src[((size_t)b * N + sr) * CDIM + c];
}

// ---------------- fused final LN (cls rows) + classification head ----------------
__global__ __launch_bounds__(128)
void head_kernel(const float* __restrict__ h, const float* __restrict__ g,
                 const float* __restrict__ bb, const float* __restrict__ W,
                 const float* __restrict__ wb, float* __restrict__ out, int N) {
    int b = blockIdx.x;
    const float* xr = h + (size_t)(b * N) * CDIM;
    __shared__ float sm[CDIM];
    int t = threadIdx.x;
    float v[3];
    float s = 0.f, s2 = 0.f;
#pragma unroll
    for (int l = 0; l < 3; l++) { v[l] = xr[t + 128 * l]; s += v[l]; s2 += v[l] * v[l]; }
#pragma unroll
    for (int o = 16; o; o >>= 1) {
        s  += __shfl_xor_sync(~0u, s, o);
        s2 += __shfl_xor_sync(~0u, s2, o);
    }
    __shared__ float ws[4], ws2[4];
    if ((t & 31) == 0) { ws[t >> 5] = s; ws2[t >> 5] = s2; }
    __syncthreads();
    s  = ws[0] + ws[1] + ws[2] + ws[3];
    s2 = ws2[0] + ws2[1] + ws2[2] + ws2[3];
    float mean = s * (1.f / CDIM);
    float var  = s2 * (1.f / CDIM) - mean * mean;
    float r = rsqrtf(var + EPSLN);
#pragma unroll
    for (int l = 0; l < 3; l++) {
        int c = t + 128 * l;
        sm[c] = (v[l] - mean) * r * g[c] + bb[c];
    }
    __syncthreads();
    if (t < NCLS) {
        float acc = wb[t];
        for (int k = 0; k < CDIM; k++)
            acc += sm[k] * W[k * NCLS + t];
        out[b * NCLS + t] = acc;
    }
}

// ---------------- launch ----------------
extern "C" void kernel_launch(void* const* d_in, const int* in_sizes, int n_in,
                              void* d_out, int out_size) {
    const float* x        = (const float*)d_in[0];
    const float* patch_w  = (const float*)d_in[1];
    const float* patch_b  = (const float*)d_in[2];
    const float* cls_tok  = (const float*)d_in[3];
    const float* pos_emb  = (const float*)d_in[4];
    const float* ln1_g    = (const float*)d_in[5];
    const float* ln1_b    = (const float*)d_in[6];
    const float* qkv_w    = (const float*)d_in[7];
    const float* qkv_b    = (const float*)d_in[8];
    const float* proj_w   = (const float*)d_in[9];
    const float* proj_b   = (const float*)d_in[10];
    const float* ln2_g    = (const float*)d_in[11];
    const float* ln2_b    = (const float*)d_in[12];
    const float* fc1_w    = (const float*)d_in[13];
    const float* fc1_b    = (const float*)d_in[14];
    const float* fc2_w    = (const float*)d_in[15];
    const float* fc2_b    = (const float*)d_in[16];
    const float* norm_g   = (const float*)d_in[17];
    const float* norm_b   = (const float*)d_in[18];
    const float* head_w   = (const float*)d_in[19];
    const float* head_b   = (const float*)d_in[20];

    float *h[2], *pembed, *scoresb;
    int* idxb;
    __half *wth, *wtl, *lnh, *lnl, *qkvh, *qkvl, *vth, *vtl, *ph, *pl, *aoh, *aol, *mlph, *mlpl, *pxh, *pxl;
    cudaGetSymbolAddress((void**)&h[0], g_h0);
    cudaGetSymbolAddress((void**)&h[1], g_h1);
    cudaGetSymbolAddress((void**)&pembed, g_pembed);
    cudaGetSymbolAddress((void**)&scoresb, g_scores);
    cudaGetSymbolAddress((void**)&idxb, g_idx);
    cudaGetSymbolAddress((void**)&wth, g_wth);
    cudaGetSymbolAddress((void**)&wtl, g_wtl);
    cudaGetSymbolAddress((void**)&lnh, g_lnh);
    cudaGetSymbolAddress((void**)&lnl, g_lnl);
    cudaGetSymbolAddress((void**)&qkvh, g_qkvh);
    cudaGetSymbolAddress((void**)&qkvl, g_qkvl);
    cudaGetSymbolAddress((void**)&vth, g_vth);
    cudaGetSymbolAddress((void**)&vtl, g_vtl);
    cudaGetSymbolAddress((void**)&ph, g_ph);
    cudaGetSymbolAddress((void**)&pl, g_pl);
    cudaGetSymbolAddress((void**)&aoh, g_aoh);
    cudaGetSymbolAddress((void**)&aol, g_aol);
    cudaGetSymbolAddress((void**)&mlph, g_mlph);
    cudaGetSymbolAddress((void**)&mlpl, g_mlpl);
    cudaGetSymbolAddress((void**)&pxh, g_pxh);
    cudaGetSymbolAddress((void**)&pxl, g_pxl);

    // dynamic smem opt-in
    cudaFuncSetAttribute(gemm_fp16<0, true,  false>, cudaFuncAttributeMaxDynamicSharedMemorySize, GEMM_SMEM);
    cudaFuncSetAttribute(gemm_fp16<0, false, true >, cudaFuncAttributeMaxDynamicSharedMemorySize, GEMM_SMEM);
    cudaFuncSetAttribute(gemm_fp16<1, true,  false>, cudaFuncAttributeMaxDynamicSharedMemorySize, GEMM_SMEM);
    cudaFuncSetAttribute(gemm_fp16<2, false, true >, cudaFuncAttributeMaxDynamicSharedMemorySize, GEMM_SMEM);
    cudaFuncSetAttribute(qk_softmax, cudaFuncAttributeMaxDynamicSharedMemorySize, QKS_SMEM);

    // ---- weight transpose + split (once per call) ----
    {
        dim3 blk(32, 8);
        wsplit_kernel<<<dim3(768 / 32, 384 / 32, 1), blk>>>(patch_w, 0, wth + OFF_PATCH, wtl + OFF_PATCH, 0, 768, 384);
        wsplit_kernel<<<dim3(384 / 32, 1152 / 32, 12), blk>>>(qkv_w, (size_t)384 * 1152, wth + OFF_QKV, wtl + OFF_QKV, SZ_QKV, 384, 1152);
        wsplit_kernel<<<dim3(384 / 32, 384 / 32, 12), blk>>>(proj_w, (size_t)384 * 384, wth + OFF_PROJ, wtl + OFF_PROJ, SZ_PROJ, 384, 384);
        wsplit_kernel<<<dim3(384 / 32, 1536 / 32, 12), blk>>>(fc1_w, (size_t)384 * 1536, wth + OFF_FC1, wtl + OFF_FC1, SZ_FC1, 384, 1536);
        wsplit_kernel<<<dim3(1536 / 32, 384 / 32, 12), blk>>>(fc2_w, (size_t)1536 * 384, wth + OFF_FC2, wtl + OFF_FC2, SZ_FC2, 1536, 384);
    }

    // ---- patch embed ----
    {
        int tot = BATCH * NPATCH * 768;
        patchify_kernel<<<(tot + 255) / 256, 256>>>(x, pxh, pxl);
        int M = BATCH * NPATCH;
        gemm_fp16<0, true, false><<<dim3(CDIM / 64, (M + 127) / 128), 256, GEMM_SMEM>>>(
            pxh, pxl, wth + OFF_PATCH, wtl + OFF_PATCH, patch_b, nullptr,
            pembed, nullptr, nullptr, M, 768, CDIM, INV_WSCALE);
        int tot2 = BATCH * MAXN * CDIM;
        assemble_kernel<<<(tot2 + 255) / 256, 256>>>(pembed, cls_tok, pos_emb, h[0]);
    }

    int cur = 0;
    int N = MAXN;
    for (int l = 0; l < LAYERS; l++) {
        int M = BATCH * N;
        // attention
        ln_kernel<<<M, 128>>>(h[cur], ln1_g + l * CDIM, ln1_b + l * CDIM, lnh, lnl);
        gemm_fp16<0, false, true><<<dim3(1152 / 64, (M + 127) / 128), 256, GEMM_SMEM>>>(
            lnh, lnl, wth + OFF_QKV + (size_t)l * SZ_QKV, wtl + OFF_QKV + (size_t)l * SZ_QKV,
            qkv_b + l * 1152, nullptr, nullptr, qkvh, qkvl, M, CDIM, 1152, INV_WSCALE);
        vt_kernel<<<dim3(ASTRIDE / 32, 2, BATCH * HEADS), dim3(32, 8)>>>(qkvh, qkvl, vth, vtl, N);
        int nt = (N + 63) / 64;
        qk_softmax<<<dim3(nt, BATCH * HEADS), 128, QKS_SMEM>>>(qkvh, qkvl, ph, pl, N);
        av_fp16<<<dim3(nt, BATCH * HEADS), 128>>>(ph, pl, vth, vtl, aoh, aol, N);
        gemm_fp16<1, true, false><<<dim3(CDIM / 64, (M + 127) / 128), 256, GEMM_SMEM>>>(
            aoh, aol, wth + OFF_PROJ + (size_t)l * SZ_PROJ, wtl + OFF_PROJ + (size_t)l * SZ_PROJ,
            proj_b + l * CDIM, h[cur], h[cur], nullptr, nullptr, M, CDIM, CDIM, INV_WSCALE);
        // prune
        if (l == 2 || l == 4 || l == 6) {
            int keep = (l == 2) ? 176 : (l == 4) ? 149 : 119;
            int Ntok = N - 1;
            scoremean_kernel<<<(BATCH * Ntok + 255) / 256, 256>>>(ph, pl, scoresb, N);
            rank_kernel<<<BATCH, 256>>>(scoresb, idxb, Ntok, keep);
            int newN = keep + 1;
            size_t tot = (size_t)BATCH * newN * CDIM;
            gather_kernel<<<(int)((tot + 255) / 256), 256>>>(h[cur], h[1 - cur], idxb, N, keep);
            cur ^= 1;
            N = newN;
            M = BATCH * N;
        }
        // mlp
        ln_kernel<<<M, 128>>>(h[cur], ln2_g + l * CDIM, ln2_b + l * CDIM, lnh, lnl);
        gemm_fp16<2, false, true><<<dim3(MLPD / 64, (M + 127) / 128), 256, GEMM_SMEM>>>(
            lnh, lnl, wth + OFF_FC1 + (size_t)l * SZ_FC1, wtl + OFF_FC1 + (size_t)l * SZ_FC1,
            fc1_b + l * MLPD, nullptr, nullptr, mlph, mlpl, M, CDIM, MLPD, INV_WSCALE);
        gemm_fp16<1, true, false><<<dim3(CDIM / 64, (M + 127) / 128), 256, GEMM_SMEM>>>(
            mlph, mlpl, wth + OFF_FC2 + (size_t)l * SZ_FC2, wtl + OFF_FC2 + (size_t)l * SZ_FC2,
            fc2_b + l * CDIM, h[cur], h[cur], nullptr, nullptr, M, MLPD, CDIM, INV_WSCALE);
    }

    head_kernel<<<BATCH, 128>>>(h[cur], norm_g, norm_b, head_w, head_b, (float*)d_out, N);
}

// round 10
// speedup vs baseline: 2.4426x; 1.1547x over previous
// THEORY (round 10): fuse QK^T -> online softmax -> P.V into one flash_attn
// kernel. P stays in registers (packsplit to fp16 hi/lo in-register, exactly
// the fragment layout the S accumulators already have); V fragments are built
// from smem via paired 16-bit loads, deleting the vt kernel and the
// Ph/Pl/vth/vtl buffers (~2.2 GB DRAM traffic per launch removed) and 24
// kernel launches. CLS-row logits are side-written by the i0==0 CTA for the
// prune path (cls_prep computes per-(b,h) softmax stats; scoremean uses them).
// GEMMs stay at the round-7 version (measured at the legacy-HMMA floor).
// Predict dur_us 8519 -> ~7600-7950, rel_err ~4.4e-6.
#include <cuda_runtime.h>
#include <cuda_fp16.h>
#include <stdint.h>
#include <stddef.h>
#include <math.h>

#define BATCH   64
#define CDIM    384
#define HEADS   6
#define MLPD    1536
#define LAYERS  12
#define NPATCH  196
#define MAXN    197
#define NCLS    100
#define EPSLN   1e-6f
#define SCALE   0.125f
#define ASTRIDE 224
#define WSCALE     64.f
#define INV_WSCALE (1.f/64.f)

#define SZ_PATCH (768*384)
#define SZ_QKV   (384*1152)
#define SZ_PROJ  (384*384)
#define SZ_FC1   (384*1536)
#define SZ_FC2   (1536*384)
#define OFF_PATCH 0
#define OFF_QKV   (SZ_PATCH)
#define OFF_PROJ  (OFF_QKV + 12*SZ_QKV)
#define OFF_FC1   (OFF_PROJ + 12*SZ_PROJ)
#define OFF_FC2   (OFF_FC1 + 12*SZ_FC1)
#define WTOTAL    (OFF_FC2 + 12*SZ_FC2)

__device__ float  g_h0[(size_t)BATCH * MAXN * CDIM];
__device__ float  g_h1[(size_t)BATCH * MAXN * CDIM];
__device__ float  g_pembed[(size_t)BATCH * NPATCH * CDIM];
__device__ float  g_scores[BATCH * NPATCH];
__device__ int    g_idx[BATCH * NPATCH];
__device__ float  g_cls[(size_t)BATCH * HEADS * ASTRIDE];
__device__ float  g_clsms[(size_t)BATCH * HEADS * 2];

__device__ __half g_wth[(size_t)WTOTAL];
__device__ __half g_wtl[(size_t)WTOTAL];
__device__ __half g_lnh[(size_t)BATCH * MAXN * CDIM];
__device__ __half g_lnl[(size_t)BATCH * MAXN * CDIM];
__device__ __half g_qkvh[(size_t)BATCH * MAXN * 1152];
__device__ __half g_qkvl[(size_t)BATCH * MAXN * 1152];
__device__ __half g_aoh[(size_t)BATCH * MAXN * CDIM];
__device__ __half g_aol[(size_t)BATCH * MAXN * CDIM];
__device__ __half g_mlph[(size_t)BATCH * MAXN * MLPD];
__device__ __half g_mlpl[(size_t)BATCH * MAXN * MLPD];
__device__ __half g_pxh[(size_t)BATCH * NPATCH * 768];
__device__ __half g_pxl[(size_t)BATCH * NPATCH * 768];

__device__ __forceinline__ void split_h(float v, __half& h, __half& l) {
    h = __float2half_rn(v);
    l = __float2half_rn(v - __half2float(h));
}

__device__ __forceinline__ void packsplit(float a, float b, unsigned& hi, unsigned& lo) {
    __half ah = __float2half_rn(a);
    __half al = __float2half_rn(a - __half2float(ah));
    __half bh = __float2half_rn(b);
    __half bl = __float2half_rn(b - __half2float(bh));
    hi = (unsigned)__half_as_ushort(ah) | ((unsigned)__half_as_ushort(bh) << 16);
    lo = (unsigned)__half_as_ushort(al) | ((unsigned)__half_as_ushort(bl) << 16);
}

__device__ __forceinline__ void mma16(float* c, const unsigned* a, const unsigned* b) {
    asm volatile(
        "mma.sync.aligned.m16n8k16.row.col.f32.f16.f16.f32 "
        "{%0,%1,%2,%3},{%4,%5,%6,%7},{%8,%9},{%0,%1,%2,%3};"
        : "+f"(c[0]), "+f"(c[1]), "+f"(c[2]), "+f"(c[3])
        : "r"(a[0]), "r"(a[1]), "r"(a[2]), "r"(a[3]), "r"(b[0]), "r"(b[1]));
}

__device__ __forceinline__ unsigned cvta_s(const void* p) {
    unsigned a;
    asm("{ .reg .u64 t; cvta.to.shared.u64 t, %1; cvt.u32.u64 %0, t; }" : "=r"(a) : "l"(p));
    return a;
}

__device__ __forceinline__ void cp16(unsigned dst, const void* src, unsigned sz) {
    asm volatile("cp.async.cg.shared.global [%0], [%1], 16, %2;"
                 :: "r"(dst), "l"(src), "r"(sz) : "memory");
}
#define CP_COMMIT() asm volatile("cp.async.commit_group;" ::: "memory")
#define CP_WAIT1()  asm volatile("cp.async.wait_group 1;" ::: "memory")
#define CP_WAIT0()  asm volatile("cp.async.wait_group 0;" ::: "memory")

// ---------------- fp16x3 GEMM with cp.async double buffering ----------------
#define GEMM_SMEM 61440

__device__ __forceinline__ void gemm_issue(
    unsigned sb, const __half* Ah, const __half* Al,
    const __half* Bth, const __half* Btl,
    int M, int K, int m0, int n0, int t, int c) {
    int p = c & 1;
    int kb = c * 32;
#pragma unroll
    for (int s = 0; s < 2; s++) {
        const __half* asrc = s ? Al : Ah;
#pragma unroll
        for (int it = 0; it < 2; it++) {
            int idx = t + it * 256;
            int row = idx >> 2, c4 = idx & 3;
            int gm = m0 + row;
            int gmc = (gm < M) ? gm : (M - 1);
            const __half* src = asrc + (size_t)gmc * K + kb + 8 * c4;
            unsigned dst = sb + (unsigned)(p * 10240 + s * 5120 + row * 40 + 8 * c4) * 2u;
            cp16(dst, src, (gm < M) ? 16u : 0u);
        }
        const __half* bsrc = s ? Btl : Bth;
        int brow = t >> 2, bc4 = t & 3;
        const __half* srcb = bsrc + (size_t)(n0 + brow) * K + kb + 8 * bc4;
        unsigned dstb = sb + (unsigned)(20480 + p * 5120 + s * 2560 + brow * 40 + 8 * bc4) * 2u;
        cp16(dstb, srcb, 16u);
    }
    CP_COMMIT();
}

template<int EPI, bool OF32, bool OHALF>
__global__ __launch_bounds__(256, 2)
void gemm_fp16(const __half* __restrict__ Ah, const __half* __restrict__ Al,
               const __half* __restrict__ Bth, const __half* __restrict__ Btl,
               const float* __restrict__ bias, const float* __restrict__ res,
               float* __restrict__ C32, __half* __restrict__ Ch, __half* __restrict__ Cl,
               int M, int K, int Nout, float oscale) {
    extern __shared__ __half smp[];
    unsigned sb = cvta_s(smp);
    int t = threadIdx.x, lane = t & 31, wid = t >> 5;
    int g = lane >> 2, q = lane & 3;
    int wm = wid >> 1, wn = wid & 1;
    int m0 = blockIdx.y * 128, n0 = blockIdx.x * 64;
    float acc[2][4][4] = {};
    int nch = K >> 5;

    gemm_issue(sb, Ah, Al, Bth, Btl, M, K, m0, n0, t, 0);
    for (int c = 0; c < nch; c++) {
        if (c + 1 < nch) {
            gemm_issue(sb, Ah, Al, Bth, Btl, M, K, m0, n0, t, c + 1);
            CP_WAIT1();
        } else {
            CP_WAIT0();
        }
        __syncthreads();
        int p = c & 1;
        const __half* Ab = smp + p * 10240;
        const __half* Bb = smp + 20480 + p * 5120;
#pragma unroll
        for (int ks = 0; ks < 2; ks++) {
            int kb = ks * 16;
            unsigned aH[2][4], aL[2][4];
#pragma unroll
            for (int tm = 0; tm < 2; tm++) {
                int r0 = wm * 32 + tm * 16;
                const __half* a0 = Ab + (r0 + g) * 40;
                const __half* a8 = Ab + (r0 + g + 8) * 40;
                aH[tm][0] = *(const unsigned*)(a0 + kb + 2 * q);
                aH[tm][1] = *(const unsigned*)(a8 + kb + 2 * q);
                aH[tm][2] = *(const unsigned*)(a0 + kb + 2 * q + 8);
                aH[tm][3] = *(const unsigned*)(a8 + kb + 2 * q + 8);
                const __half* l0 = a0 + 5120;
                const __half* l8 = a8 + 5120;
                aL[tm][0] = *(const unsigned*)(l0 + kb + 2 * q);
                aL[tm][1] = *(const unsigned*)(l8 + kb + 2 * q);
                aL[tm][2] = *(const unsigned*)(l0 + kb + 2 * q + 8);
                aL[tm][3] = *(const unsigned*)(l8 + kb + 2 * q + 8);
            }
            unsigned bH[4][2], bL[4][2];
#pragma unroll
            for (int tn = 0; tn < 4; tn++) {
                int n = wn * 32 + tn * 8 + g;
                const __half* b0 = Bb + n * 40;
                bH[tn][0] = *(const unsigned*)(b0 + kb + 2 * q);
                bH[tn][1] = *(const unsigned*)(b0 + kb + 2 * q + 8);
                const __half* bl = b0 + 2560;
                bL[tn][0] = *(const unsigned*)(bl + kb + 2 * q);
                bL[tn][1] = *(const unsigned*)(bl + kb + 2 * q + 8);
            }
#pragma unroll
            for (int tm = 0; tm < 2; tm++)
#pragma unroll
                for (int tn = 0; tn < 4; tn++) {
                    mma16(acc[tm][tn], aH[tm], bH[tn]);
                    mma16(acc[tm][tn], aH[tm], bL[tn]);
                    mma16(acc[tm][tn], aL[tm], bH[tn]);
                }
        }
        __syncthreads();
    }

#pragma unroll
    for (int tm = 0; tm < 2; tm++) {
#pragma unroll
        for (int tn = 0; tn < 4; tn++) {
            int col = n0 + wn * 32 + tn * 8 + 2 * q;
            int r0 = m0 + wm * 32 + tm * 16;
#pragma unroll
            for (int hf = 0; hf < 2; hf++) {
                int gm = r0 + g + 8 * hf;
                if (gm >= M) continue;
#pragma unroll
                for (int cc = 0; cc < 2; cc++) {
                    float v = acc[tm][tn][hf * 2 + cc] * oscale + bias[col + cc];
                    if (EPI == 1) v += res[(size_t)gm * Nout + col + cc];
                    if (EPI == 2) v = 0.5f * v * (1.f + erff(v * 0.70710678118654752f));
                    if (OF32) C32[(size_t)gm * Nout + col + cc] = v;
                    if (OHALF) {
                        __half hh, ll;
                        split_h(v, hh, ll);
                        Ch[(size_t)gm * Nout + col + cc] = hh;
                        Cl[(size_t)gm * Nout + col + cc] = ll;
                    }
                }
            }
        }
    }
}

// ---------------- weight transpose + split ----------------
__global__ void wsplit_kernel(const float* __restrict__ W, size_t in_lstride,
                              __half* __restrict__ oh, __half* __restrict__ ol,
                              size_t out_lstride, int K, int N) {
    __shared__ float tile[32][33];
    int k0 = blockIdx.x * 32, n0 = blockIdx.y * 32;
    const float* Wl = W + (size_t)blockIdx.z * in_lstride;
    __half* ohl = oh + (size_t)blockIdx.z * out_lstride;
    __half* oll = ol + (size_t)blockIdx.z * out_lstride;
    int tx = threadIdx.x, ty = threadIdx.y;
#pragma unroll
    for (int i = 0; i < 4; i++)
        tile[ty + 8 * i][tx] = Wl[(size_t)(k0 + ty + 8 * i) * N + n0 + tx];
    __syncthreads();
#pragma unroll
    for (int i = 0; i < 4; i++) {
        int n = n0 + ty + 8 * i, k = k0 + tx;
        float v = tile[tx][ty + 8 * i] * WSCALE;
        __half h, l;
        split_h(v, h, l);
        ohl[(size_t)n * K + k] = h;
        oll[(size_t)n * K + k] = l;
    }
}

// ---------------- patchify + split ----------------
__global__ void patchify_kernel(const float* __restrict__ x,
                                __half* __restrict__ ph, __half* __restrict__ pl) {
    int i = blockIdx.x * 256 + threadIdx.x;
    const int TOT = BATCH * NPATCH * 768;
    if (i >= TOT) return;
    int k  = i % 768;
    int tt = (i / 768) % NPATCH;
    int b  = i / (768 * NPATCH);
    int ch = k >> 8, py = (k >> 4) & 15, px = k & 15;
    int gy = tt / 14, gx = tt % 14;
    float v = x[(((size_t)b * 3 + ch) * 224 + gy * 16 + py) * 224 + gx * 16 + px];
    split_h(v, ph[i], pl[i]);
}

// ---------------- assemble ----------------
__global__ void assemble_kernel(const float* __restrict__ pe, const float* __restrict__ cls,
                                const float* __restrict__ pos, float* __restrict__ h) {
    int i = blockIdx.x * 256 + threadIdx.x;
    const int TOT = BATCH * MAXN * CDIM;
    if (i >= TOT) return;
    int c = i % CDIM;
    int r = (i / CDIM) % MAXN;
    int b = i / (CDIM * MAXN);
    float v = (r == 0) ? cls[c] : pe[((size_t)b * NPATCH + (r - 1)) * CDIM + c];
    h[i] = v + pos[r * CDIM + c];
}

// ---------------- LayerNorm -> split halves ----------------
__global__ __launch_bounds__(128)
void ln_kernel(const float* __restrict__ x, const float* __restrict__ g,
               const float* __restrict__ bb, __half* __restrict__ yh, __half* __restrict__ yl) {
    size_t row = blockIdx.x;
    const float* xr = x + row * CDIM;
    int t = threadIdx.x;
    float v[3];
    float s = 0.f, s2 = 0.f;
#pragma unroll
    for (int l = 0; l < 3; l++) { v[l] = xr[t + 128 * l]; s += v[l]; s2 += v[l] * v[l]; }
#pragma unroll
    for (int o = 16; o; o >>= 1) {
        s  += __shfl_xor_sync(~0u, s, o);
        s2 += __shfl_xor_sync(~0u, s2, o);
    }
    __shared__ float ws[4], ws2[4];
    if ((t & 31) == 0) { ws[t >> 5] = s; ws2[t >> 5] = s2; }
    __syncthreads();
    s  = ws[0] + ws[1] + ws[2] + ws[3];
    s2 = ws2[0] + ws2[1] + ws2[2] + ws2[3];
    float mean = s * (1.f / CDIM);
    float var  = s2 * (1.f / CDIM) - mean * mean;
    float r = rsqrtf(var + EPSLN);
#pragma unroll
    for (int l = 0; l < 3; l++) {
        int c = t + 128 * l;
        float o = (v[l] - mean) * r * g[c] + bb[c];
        split_h(o, yh[row * CDIM + c], yl[row * CDIM + c]);
    }
}

// ---------------- fused flash attention ----------------
#define FLASH_SMEM 55296

__global__ __launch_bounds__(128)
void flash_attn(const __half* __restrict__ qkvh, const __half* __restrict__ qkvl,
                __half* __restrict__ aoh, __half* __restrict__ aol,
                float* __restrict__ clslog, int N) {
    extern __shared__ __half fsm[];
    __half* Qs = fsm;            // [2][64][72]
    __half* Ks = fsm + 9216;     // [2][64][72]
    __half* Vs = fsm + 18432;    // [2][64 tok][72 dim]
    int bh = blockIdx.y;
    int b = bh / HEADS, hh = bh % HEADS;
    int i0 = blockIdx.x * 64;
    int t = threadIdx.x, lane = t & 31, wid = t >> 5;
    int g = lane >> 2, q = lane & 3;
    const uint4 z4 = make_uint4(0, 0, 0, 0);

#pragma unroll
    for (int s = 0; s < 2; s++) {
        const __half* src = s ? qkvl : qkvh;
#pragma unroll
        for (int it = 0; it < 4; it++) {
            int idx = t + it * 128;
            int row = idx >> 3, c = idx & 7;
            int gi = i0 + row;
            uint4 v = z4;
            if (gi < N) v = *(const uint4*)&src[((size_t)b * N + gi) * 1152 + hh * 64 + 8 * c];
            *(uint4*)&Qs[s * 4608 + row * 72 + 8 * c] = v;
        }
    }

    float m_lo = -1e30f, m_hi = -1e30f, s_lo = 0.f, s_hi = 0.f;
    float acc_o[8][4] = {};
    int ntj = (N + 63) >> 6;

    for (int jt = 0; jt < ntj; jt++) {
        int j0 = jt * 64;
        __syncthreads();
#pragma unroll
        for (int s = 0; s < 2; s++) {
            const __half* src = s ? qkvl : qkvh;
#pragma unroll
            for (int it = 0; it < 4; it++) {
                int idx = t + it * 128;
                int row = idx >> 3, c = idx & 7;
                int gj = j0 + row;
                uint4 vk = z4, vv = z4;
                if (gj < N) {
                    size_t base = ((size_t)b * N + gj) * 1152 + hh * 64 + 8 * c;
                    vk = *(const uint4*)&src[base + 384];
                    vv = *(const uint4*)&src[base + 768];
                }
                *(uint4*)&Ks[s * 4608 + row * 72 + 8 * c] = vk;
                *(uint4*)&Vs[s * 4608 + row * 72 + 8 * c] = vv;
            }
        }
        __syncthreads();

        float sa[8][4] = {};
#pragma unroll
        for (int ks = 0; ks < 4; ks++) {
            int kb = ks * 16;
            unsigned aH[4], aL[4];
            {
                const __half* a0 = Qs + (wid * 16 + g) * 72;
                const __half* a8 = Qs + (wid * 16 + g + 8) * 72;
                aH[0] = *(const unsigned*)(a0 + kb + 2 * q);
                aH[1] = *(const unsigned*)(a8 + kb + 2 * q);
                aH[2] = *(const unsigned*)(a0 + kb + 2 * q + 8);
                aH[3] = *(const unsigned*)(a8 + kb + 2 * q + 8);
                aL[0] = *(const unsigned*)(a0 + 4608 + kb + 2 * q);
                aL[1] = *(const unsigned*)(a8 + 4608 + kb + 2 * q);
                aL[2] = *(const unsigned*)(a0 + 4608 + kb + 2 * q + 8);
                aL[3] = *(const unsigned*)(a8 + 4608 + kb + 2 * q + 8);
            }
            unsigned bH[8][2], bL[8][2];
#pragma unroll
            for (int tn = 0; tn < 8; tn++) {
                const __half* b0 = Ks + (tn * 8 + g) * 72;
                bH[tn][0] = *(const unsigned*)(b0 + kb + 2 * q);
                bH[tn][1] = *(const unsigned*)(b0 + kb + 2 * q + 8);
                bL[tn][0] = *(const unsigned*)(b0 + 4608 + kb + 2 * q);
                bL[tn][1] = *(const unsigned*)(b0 + 4608 + kb + 2 * q + 8);
            }
#pragma unroll
            for (int tn = 0; tn < 8; tn++) {
                mma16(sa[tn], aH, bH[tn]);
                mma16(sa[tn], aH, bL[tn]);
                mma16(sa[tn], aL, bH[tn]);
            }
        }

#pragma unroll
        for (int tn = 0; tn < 8; tn++) {
#pragma unroll
            for (int r = 0; r < 4; r++) {
                int col = j0 + tn * 8 + 2 * q + (r & 1);
                float v = sa[tn][r] * SCALE;
                sa[tn][r] = (col < N) ? v : -1e30f;
            }
        }
        if (blockIdx.x == 0 && wid == 0 && g == 0) {
#pragma unroll
            for (int tn = 0; tn < 8; tn++) {
#pragma unroll
                for (int r = 0; r < 2; r++) {
                    int col = j0 + tn * 8 + 2 * q + r;
                    if (col < ASTRIDE) clslog[(size_t)bh * ASTRIDE + col] = sa[tn][r];
                }
            }
        }

        float mt_lo = -1e30f, mt_hi = -1e30f;
#pragma unroll
        for (int tn = 0; tn < 8; tn++) {
            mt_lo = fmaxf(mt_lo, fmaxf(sa[tn][0], sa[tn][1]));
            mt_hi = fmaxf(mt_hi, fmaxf(sa[tn][2], sa[tn][3]));
        }
        mt_lo = fmaxf(mt_lo, __shfl_xor_sync(~0u, mt_lo, 1));
        mt_lo = fmaxf(mt_lo, __shfl_xor_sync(~0u, mt_lo, 2));
        mt_hi = fmaxf(mt_hi, __shfl_xor_sync(~0u, mt_hi, 1));
        mt_hi = fmaxf(mt_hi, __shfl_xor_sync(~0u, mt_hi, 2));
        float mn_lo = fmaxf(m_lo, mt_lo), mn_hi = fmaxf(m_hi, mt_hi);
        float al_lo = expf(m_lo - mn_lo), al_hi = expf(m_hi - mn_hi);
        m_lo = mn_lo; m_hi = mn_hi;
        float ts_lo = 0.f, ts_hi = 0.f;
#pragma unroll
        for (int tn = 0; tn < 8; tn++) {
            sa[tn][0] = expf(sa[tn][0] - m_lo) * 256.f;
            sa[tn][1] = expf(sa[tn][1] - m_lo) * 256.f;
            sa[tn][2] = expf(sa[tn][2] - m_hi) * 256.f;
            sa[tn][3] = expf(sa[tn][3] - m_hi) * 256.f;
            ts_lo += sa[tn][0] + sa[tn][1];
            ts_hi += sa[tn][2] + sa[tn][3];
        }
        ts_lo += __shfl_xor_sync(~0u, ts_lo, 1);
        ts_lo += __shfl_xor_sync(~0u, ts_lo, 2);
        ts_hi += __shfl_xor_sync(~0u, ts_hi, 1);
        ts_hi += __shfl_xor_sync(~0u, ts_hi, 2);
        s_lo = s_lo * al_lo + ts_lo;
        s_hi = s_hi * al_hi + ts_hi;
#pragma unroll
        for (int tn = 0; tn < 8; tn++) {
            acc_o[tn][0] *= al_lo; acc_o[tn][1] *= al_lo;
            acc_o[tn][2] *= al_hi; acc_o[tn][3] *= al_hi;
        }

#pragma unroll
        for (int ks = 0; ks < 4; ks++) {
            unsigned aH[4], aL[4];
            packsplit(sa[2 * ks][0],     sa[2 * ks][1],     aH[0], aL[0]);
            packsplit(sa[2 * ks][2],     sa[2 * ks][3],     aH[1], aL[1]);
            packsplit(sa[2 * ks + 1][0], sa[2 * ks + 1][1], aH[2], aL[2]);
            packsplit(sa[2 * ks + 1][2], sa[2 * ks + 1][3], aH[3], aL[3]);
            int r0 = ks * 16 + 2 * q;
            unsigned bH[8][2], bL[8][2];
#pragma unroll
            for (int tn = 0; tn < 8; tn++) {
                int n = tn * 8 + g;
                bH[tn][0] = (unsigned)__half_as_ushort(Vs[r0 * 72 + n]) |
                            ((unsigned)__half_as_ushort(Vs[(r0 + 1) * 72 + n]) << 16);
                bH[tn][1] = (unsigned)__half_as_ushort(Vs[(r0 + 8) * 72 + n]) |
                            ((unsigned)__half_as_ushort(Vs[(r0 + 9) * 72 + n]) << 16);
                bL[tn][0] = (unsigned)__half_as_ushort(Vs[4608 + r0 * 72 + n]) |
                            ((unsigned)__half_as_ushort(Vs[4608 + (r0 + 1) * 72 + n]) << 16);
                bL[tn][1] = (unsigned)__half_as_ushort(Vs[4608 + (r0 + 8) * 72 + n]) |
                            ((unsigned)__half_as_ushort(Vs[4608 + (r0 + 9) * 72 + n]) << 16);
            }
#pragma unroll
            for (int tn = 0; tn < 8; tn++) {
                mma16(acc_o[tn], aH, bH[tn]);
                mma16(acc_o[tn], aH, bL[tn]);
                mma16(acc_o[tn], aL, bH[tn]);
            }
        }
    }

    float inv_lo = 1.f / fmaxf(s_lo, 1e-30f);
    float inv_hi = 1.f / fmaxf(s_hi, 1e-30f);
#pragma unroll
    for (int tn = 0; tn < 8; tn++) {
#pragma unroll
        for (int r = 0; r < 4; r++) {
            int gi = i0 + wid * 16 + g + ((r >= 2) ? 8 : 0);
            if (gi >= N) continue;
            int d = tn * 8 + 2 * q + (r & 1);
            float v = acc_o[tn][r] * ((r < 2) ? inv_lo : inv_hi);
            __half hh2, ll2;
            split_h(v, hh2, ll2);
            size_t oo = ((size_t)b * N + gi) * CDIM + hh * 64 + d;
            aoh[oo] = hh2;
            aol[oo] = ll2;
        }
    }
}

// ---------------- prune helpers ----------------
__global__ __launch_bounds__(128)
void cls_prep(const float* __restrict__ cls, float* __restrict__ ms, int N) {
    int row = blockIdx.x;
    int t = threadIdx.x;
    const float* r = cls + (size_t)row * ASTRIDE;
    __shared__ float red[4];
    float mx = -1e30f;
    for (int j = t; j < N; j += 128) mx = fmaxf(mx, r[j]);
#pragma unroll
    for (int o = 16; o; o >>= 1) mx = fmaxf(mx, __shfl_xor_sync(~0u, mx, o));
    if ((t & 31) == 0) red[t >> 5] = mx;
    __syncthreads();
    mx = fmaxf(fmaxf(red[0], red[1]), fmaxf(red[2], red[3]));
    __syncthreads();
    float sum = 0.f;
    for (int j = t; j < N; j += 128) sum += expf(r[j] - mx);
#pragma unroll
    for (int o = 16; o; o >>= 1) sum += __shfl_xor_sync(~0u, sum, o);
    if ((t & 31) == 0) red[t >> 5] = sum;
    __syncthreads();
    if (t == 0) {
        ms[row * 2]     = mx;
        ms[row * 2 + 1] = red[0] + red[1] + red[2] + red[3];
    }
}

__global__ void scoremean_kernel(const float* __restrict__ cls, const float* __restrict__ ms,
                                 float* __restrict__ scores, int N) {
    int Ntok = N - 1;
    int i = blockIdx.x * 256 + threadIdx.x;
    if (i >= BATCH * Ntok) return;
    int b = i / Ntok, j = i % Ntok;
    float s = 0.f;
#pragma unroll
    for (int hh = 0; hh < HEADS; hh++) {
        int bh = b * HEADS + hh;
        s += expf(cls[(size_t)bh * ASTRIDE + 1 + j] - ms[bh * 2]) / ms[bh * 2 + 1];
    }
    scores[i] = s * (1.f / HEADS);
}

__global__ __launch_bounds__(256)
void rank_kernel(const float* __restrict__ scores, int* __restrict__ idxout, int Ntok, int keep) {
    int b = blockIdx.x;
    __shared__ float s[256];
    int t = threadIdx.x;
    if (t < Ntok) s[t] = scores[b * Ntok + t];
    __syncthreads();
    if (t < Ntok) {
        float mine = s[t];
        int r = 0;
        for (int j = 0; j < Ntok; j++)
            r += (s[j] > mine) || (s[j] == mine && j < t);
        if (r < keep) idxout[b * keep + r] = t;
    }
}

__global__ void gather_kernel(const float* __restrict__ src, float* __restrict__ dst,
                              const int* __restrict__ idx, int N, int keep) {
    int newN = keep + 1;
    size_t TOT = (size_t)BATCH * newN * CDIM;
    size_t i = (size_t)blockIdx.x * 256 + threadIdx.x;
    if (i >= TOT) return;
    int c = i % CDIM;
    int r = (i / CDIM) % newN;
    int b = i / ((size_t)CDIM * newN);
    int sr = (r == 0) ? 0 : 1 + idx[b * keep + r - 1];
    dst[i] = src[((size_t)b * N + sr) * CDIM + c];
}

// ---------------- fused final LN + head ----------------
__global__ __launch_bounds__(128)
void head_kernel(const float* __restrict__ h, const float* __restrict__ g,
                 const float* __restrict__ bb, const float* __restrict__ W,
                 const float* __restrict__ wb, float* __restrict__ out, int N) {
    int b = blockIdx.x;
    const float* xr = h + (size_t)(b * N) * CDIM;
    __shared__ float sm[CDIM];
    int t = threadIdx.x;
    float v[3];
    float s = 0.f, s2 = 0.f;
#pragma unroll
    for (int l = 0; l < 3; l++) { v[l] = xr[t + 128 * l]; s += v[l]; s2 += v[l] * v[l]; }
#pragma unroll
    for (int o = 16; o; o >>= 1) {
        s  += __shfl_xor_sync(~0u, s, o);
        s2 += __shfl_xor_sync(~0u, s2, o);
    }
    __shared__ float ws[4], ws2[4];
    if ((t & 31) == 0) { ws[t >> 5] = s; ws2[t >> 5] = s2; }
    __syncthreads();
    s  = ws[0] + ws[1] + ws[2] + ws[3];
    s2 = ws2[0] + ws2[1] + ws2[2] + ws2[3];
    float mean = s * (1.f / CDIM);
    float var  = s2 * (1.f / CDIM) - mean * mean;
    float r = rsqrtf(var + EPSLN);
#pragma unroll
    for (int l = 0; l < 3; l++) {
        int c = t + 128 * l;
        sm[c] = (v[l] - mean) * r * g[c] + bb[c];
    }
    __syncthreads();
    if (t < NCLS) {
        float acc = wb[t];
        for (int k = 0; k < CDIM; k++)
            acc += sm[k] * W[k * NCLS + t];
        out[b * NCLS + t] = acc;
    }
}

// ---------------- launch ----------------
extern "C" void kernel_launch(void* const* d_in, const int* in_sizes, int n_in,
                              void* d_out, int out_size) {
    const float* x        = (const float*)d_in[0];
    const float* patch_w  = (const float*)d_in[1];
    const float* patch_b  = (const float*)d_in[2];
    const float* cls_tok  = (const float*)d_in[3];
    const float* pos_emb  = (const float*)d_in[4];
    const float* ln1_g    = (const float*)d_in[5];
    const float* ln1_b    = (const float*)d_in[6];
    const float* qkv_w    = (const float*)d_in[7];
    const float* qkv_b    = (const float*)d_in[8];
    const float* proj_w   = (const float*)d_in[9];
    const float* proj_b   = (const float*)d_in[10];
    const float* ln2_g    = (const float*)d_in[11];
    const float* ln2_b    = (const float*)d_in[12];
    const float* fc1_w    = (const float*)d_in[13];
    const float* fc1_b    = (const float*)d_in[14];
    const float* fc2_w    = (const float*)d_in[15];
    const float* fc2_b    = (const float*)d_in[16];
    const float* norm_g   = (const float*)d_in[17];
    const float* norm_b   = (const float*)d_in[18];
    const float* head_w   = (const float*)d_in[19];
    const float* head_b   = (const float*)d_in[20];

    float *h[2], *pembed, *scoresb, *clsb, *clsms;
    int* idxb;
    __half *wth, *wtl, *lnh, *lnl, *qkvh, *qkvl, *aoh, *aol, *mlph, *mlpl, *pxh, *pxl;
    cudaGetSymbolAddress((void**)&h[0], g_h0);
    cudaGetSymbolAddress((void**)&h[1], g_h1);
    cudaGetSymbolAddress((void**)&pembed, g_pembed);
    cudaGetSymbolAddress((void**)&scoresb, g_scores);
    cudaGetSymbolAddress((void**)&idxb, g_idx);
    cudaGetSymbolAddress((void**)&clsb, g_cls);
    cudaGetSymbolAddress((void**)&clsms, g_clsms);
    cudaGetSymbolAddress((void**)&wth, g_wth);
    cudaGetSymbolAddress((void**)&wtl, g_wtl);
    cudaGetSymbolAddress((void**)&lnh, g_lnh);
    cudaGetSymbolAddress((void**)&lnl, g_lnl);
    cudaGetSymbolAddress((void**)&qkvh, g_qkvh);
    cudaGetSymbolAddress((void**)&qkvl, g_qkvl);
    cudaGetSymbolAddress((void**)&aoh, g_aoh);
    cudaGetSymbolAddress((void**)&aol, g_aol);
    cudaGetSymbolAddress((void**)&mlph, g_mlph);
    cudaGetSymbolAddress((void**)&mlpl, g_mlpl);
    cudaGetSymbolAddress((void**)&pxh, g_pxh);
    cudaGetSymbolAddress((void**)&pxl, g_pxl);

    cudaFuncSetAttribute(gemm_fp16<0, true,  false>, cudaFuncAttributeMaxDynamicSharedMemorySize, GEMM_SMEM);
    cudaFuncSetAttribute(gemm_fp16<0, false, true >, cudaFuncAttributeMaxDynamicSharedMemorySize, GEMM_SMEM);
    cudaFuncSetAttribute(gemm_fp16<1, true,  false>, cudaFuncAttributeMaxDynamicSharedMemorySize, GEMM_SMEM);
    cudaFuncSetAttribute(gemm_fp16<2, false, true >, cudaFuncAttributeMaxDynamicSharedMemorySize, GEMM_SMEM);
    cudaFuncSetAttribute(flash_attn, cudaFuncAttributeMaxDynamicSharedMemorySize, FLASH_SMEM);

    {
        dim3 blk(32, 8);
        wsplit_kernel<<<dim3(768 / 32, 384 / 32, 1), blk>>>(patch_w, 0, wth + OFF_PATCH, wtl + OFF_PATCH, 0, 768, 384);
        wsplit_kernel<<<dim3(384 / 32, 1152 / 32, 12), blk>>>(qkv_w, (size_t)384 * 1152, wth + OFF_QKV, wtl + OFF_QKV, SZ_QKV, 384, 1152);
        wsplit_kernel<<<dim3(384 / 32, 384 / 32, 12), blk>>>(proj_w, (size_t)384 * 384, wth + OFF_PROJ, wtl + OFF_PROJ, SZ_PROJ, 384, 384);
        wsplit_kernel<<<dim3(384 / 32, 1536 / 32, 12), blk>>>(fc1_w, (size_t)384 * 1536, wth + OFF_FC1, wtl + OFF_FC1, SZ_FC1, 384, 1536);
        wsplit_kernel<<<dim3(1536 / 32, 384 / 32, 12), blk>>>(fc2_w, (size_t)1536 * 384, wth + OFF_FC2, wtl + OFF_FC2, SZ_FC2, 1536, 384);
    }

    {
        int tot = BATCH * NPATCH * 768;
        patchify_kernel<<<(tot + 255) / 256, 256>>>(x, pxh, pxl);
        int M = BATCH * NPATCH;
        gemm_fp16<0, true, false><<<dim3(CDIM / 64, (M + 127) / 128), 256, GEMM_SMEM>>>(
            pxh, pxl, wth + OFF_PATCH, wtl + OFF_PATCH, patch_b, nullptr,
            pembed, nullptr, nullptr, M, 768, CDIM, INV_WSCALE);
        int tot2 = BATCH * MAXN * CDIM;
        assemble_kernel<<<(tot2 + 255) / 256, 256>>>(pembed, cls_tok, pos_emb, h[0]);
    }

    int cur = 0;
    int N = MAXN;
    for (int l = 0; l < LAYERS; l++) {
        int M = BATCH * N;
        ln_kernel<<<M, 128>>>(h[cur], ln1_g + l * CDIM, ln1_b + l * CDIM, lnh, lnl);
        gemm_fp16<0, false, true><<<dim3(1152 / 64, (M + 127) / 128), 256, GEMM_SMEM>>>(
            lnh, lnl, wth + OFF_QKV + (size_t)l * SZ_QKV, wtl + OFF_QKV + (size_t)l * SZ_QKV,
            qkv_b + l * 1152, nullptr, nullptr, qkvh, qkvl, M, CDIM, 1152, INV_WSCALE);
        int nt = (N + 63) / 64;
        flash_attn<<<dim3(nt, BATCH * HEADS), 128, FLASH_SMEM>>>(qkvh, qkvl, aoh, aol, clsb, N);
        gemm_fp16<1, true, false><<<dim3(CDIM / 64, (M + 127) / 128), 256, GEMM_SMEM>>>(
            aoh, aol, wth + OFF_PROJ + (size_t)l * SZ_PROJ, wtl + OFF_PROJ + (size_t)l * SZ_PROJ,
            proj_b + l * CDIM, h[cur], h[cur], nullptr, nullptr, M, CDIM, CDIM, INV_WSCALE);
        if (l == 2 || l == 4 || l == 6) {
            int keep = (l == 2) ? 176 : (l == 4) ? 149 : 119;
            int Ntok = N - 1;
            cls_prep<<<BATCH * HEADS, 128>>>(clsb, clsms, N);
            scoremean_kernel<<<(BATCH * Ntok + 255) / 256, 256>>>(clsb, clsms, scoresb, N);
            rank_kernel<<<BATCH, 256>>>(scoresb, idxb, Ntok, keep);
            int newN = keep + 1;
            size_t tot = (size_t)BATCH * newN * CDIM;
            gather_kernel<<<(int)((tot + 255) / 256), 256>>>(h[cur], h[1 - cur], idxb, N, keep);
            cur ^= 1;
            N = newN;
            M = BATCH * N;
        }
        ln_kernel<<<M, 128>>>(h[cur], ln2_g + l * CDIM, ln2_b + l * CDIM, lnh, lnl);
        gemm_fp16<2, false, true><<<dim3(MLPD / 64, (M + 127) / 128), 256, GEMM_SMEM>>>(
            lnh, lnl, wth + OFF_FC1 + (size_t)l * SZ_FC1, wtl + OFF_FC1 + (size_t)l * SZ_FC1,
            fc1_b + l * MLPD, nullptr, nullptr, mlph, mlpl, M, CDIM, MLPD, INV_WSCALE);
        gemm_fp16<1, true, false><<<dim3(CDIM / 64, (M + 127) / 128), 256, GEMM_SMEM>>>(
            mlph, mlpl, wth + OFF_FC2 + (size_t)l * SZ_FC2, wtl + OFF_FC2 + (size_t)l * SZ_FC2,
            fc2_b + l * CDIM, h[cur], h[cur], nullptr, nullptr, M, MLPD, CDIM, INV_WSCALE);
    }

    head_kernel<<<BATCH, 128>>>(h[cur], norm_g, norm_b, head_w, head_b, (float*)d_out, N);
}